// round 1
// baseline (speedup 1.0000x reference)
#include <cuda_runtime.h>

#define DM      1024
#define NHEAD   16
#define DEPTH   64
#define BATCH   4
#define SEQ     2048
#define MTOT    (BATCH*SEQ)   // 8192

// Scratch (device globals: allowed; no dynamic allocation)
__device__ float g_q[BATCH*NHEAD*SEQ*DEPTH];    // [B,H,S,64]
__device__ float g_k[BATCH*NHEAD*SEQ*DEPTH];
__device__ float g_v[BATCH*NHEAD*SEQ*DEPTH];
__device__ float g_att[BATCH*SEQ*DM];           // [B,S,1024]

// ---------------------------------------------------------------------------
// Tiled SGEMM block: C(128x128) = A[M,1024] (row-major) * W[N,1024]^T
// 256 threads, 8x8 per thread, K-tile 8, double-buffered smem.
// ---------------------------------------------------------------------------
__device__ __forceinline__ void gemm_block(const float* __restrict__ A,
                                           const float* __restrict__ W,
                                           int m0, int n0,
                                           float acc[8][8]) {
    __shared__ float As[2][8][132];
    __shared__ float Bs[2][8][132];

    const int tid = threadIdx.x;
    const int lr  = tid >> 1;            // 0..127
    const int lk  = (tid & 1) << 2;      // 0 or 4
    const int ty  = tid >> 4;            // 0..15
    const int tx  = tid & 15;            // 0..15

    const float* ag = A + (size_t)(m0 + lr) * DM + lk;
    const float* bg = W + (size_t)(n0 + lr) * DM + lk;

    float4 fa = *(const float4*)ag;
    float4 fb = *(const float4*)bg;
    As[0][lk+0][lr] = fa.x; As[0][lk+1][lr] = fa.y;
    As[0][lk+2][lr] = fa.z; As[0][lk+3][lr] = fa.w;
    Bs[0][lk+0][lr] = fb.x; Bs[0][lk+1][lr] = fb.y;
    Bs[0][lk+2][lr] = fb.z; Bs[0][lk+3][lr] = fb.w;
    __syncthreads();

    const int NT = DM / 8;  // 128 k-tiles
    #pragma unroll 1
    for (int kt = 0; kt < NT; ++kt) {
        const int cur = kt & 1;
        if (kt + 1 < NT) {
            fa = *(const float4*)(ag + (kt + 1) * 8);
            fb = *(const float4*)(bg + (kt + 1) * 8);
        }
        #pragma unroll
        for (int k = 0; k < 8; ++k) {
            float av[8], bv[8];
            float4 t0 = *(const float4*)&As[cur][k][ty * 8];
            float4 t1 = *(const float4*)&As[cur][k][ty * 8 + 4];
            av[0]=t0.x; av[1]=t0.y; av[2]=t0.z; av[3]=t0.w;
            av[4]=t1.x; av[5]=t1.y; av[6]=t1.z; av[7]=t1.w;
            float4 u0 = *(const float4*)&Bs[cur][k][tx * 8];
            float4 u1 = *(const float4*)&Bs[cur][k][tx * 8 + 4];
            bv[0]=u0.x; bv[1]=u0.y; bv[2]=u0.z; bv[3]=u0.w;
            bv[4]=u1.x; bv[5]=u1.y; bv[6]=u1.z; bv[7]=u1.w;
            #pragma unroll
            for (int i = 0; i < 8; ++i)
                #pragma unroll
                for (int j = 0; j < 8; ++j)
                    acc[i][j] = fmaf(av[i], bv[j], acc[i][j]);
        }
        if (kt + 1 < NT) {
            const int nxt = cur ^ 1;
            As[nxt][lk+0][lr] = fa.x; As[nxt][lk+1][lr] = fa.y;
            As[nxt][lk+2][lr] = fa.z; As[nxt][lk+3][lr] = fa.w;
            Bs[nxt][lk+0][lr] = fb.x; Bs[nxt][lk+1][lr] = fb.y;
            Bs[nxt][lk+2][lr] = fb.z; Bs[nxt][lk+3][lr] = fb.w;
            __syncthreads();
        }
    }
}

// ---------------------------------------------------------------------------
// Q/K/V projections: y = x @ W^T scattered to [B,H,S,64]
// grid: (N/128=8, M/128=64, 3), block 256
// ---------------------------------------------------------------------------
__global__ __launch_bounds__(256) void proj_qkv_kernel(const float* __restrict__ x,
                                                       const float* __restrict__ wq,
                                                       const float* __restrict__ wk,
                                                       const float* __restrict__ wv) {
    const int z = blockIdx.z;
    const float* w = (z == 0) ? wq : (z == 1) ? wk : wv;
    float* outb    = (z == 0) ? g_q : (z == 1) ? g_k : g_v;

    float acc[8][8];
    #pragma unroll
    for (int i = 0; i < 8; ++i)
        #pragma unroll
        for (int j = 0; j < 8; ++j) acc[i][j] = 0.f;

    const int m0 = blockIdx.y * 128;
    const int n0 = blockIdx.x * 128;
    gemm_block(x, w, m0, n0, acc);

    const int ty = threadIdx.x >> 4;
    const int tx = threadIdx.x & 15;
    #pragma unroll
    for (int i = 0; i < 8; ++i) {
        const int m  = m0 + ty * 8 + i;
        const int bb = m >> 11;          // / 2048
        const int ss = m & 2047;
        #pragma unroll
        for (int jq = 0; jq < 8; jq += 4) {
            const int n  = n0 + tx * 8 + jq;
            const int h  = n >> 6;       // / 64
            const int dd = n & 63;
            float* dst = outb + ((((size_t)bb * NHEAD + h) * SEQ + ss) * DEPTH + dd);
            *(float4*)dst = make_float4(acc[i][jq], acc[i][jq+1], acc[i][jq+2], acc[i][jq+3]);
        }
    }
}

// ---------------------------------------------------------------------------
// Flash attention: per (b,h), 64-query blocks over 2048 keys, depth 64.
// grid: (32 qtiles, 64 bh), block 256, dynamic smem 4*64*68*4 = 69632 B
// ---------------------------------------------------------------------------
__global__ __launch_bounds__(256) void attn_kernel() {
    extern __shared__ float sm[];
    float* Qt = sm;                  // [64 d][68]  d-major (scaled by 1/8)
    float* Kt = Qt + 64 * 68;        // [64 d][68]  d-major
    float* Vs = Kt + 64 * 68;        // [64 key][68] row-major
    float* Pt = Vs + 64 * 68;        // [64 key][68] key-major

    const int tid = threadIdx.x;
    const int ty  = tid >> 4;        // query sub-row group
    const int tx  = tid & 15;        // key / depth column group
    const int bh  = blockIdx.y;
    const int q0  = blockIdx.x * 64;

    const float* qg  = g_q + ((size_t)bh * SEQ + q0) * DEPTH;
    const float* kgb = g_k + (size_t)bh * SEQ * DEPTH;
    const float* vgb = g_v + (size_t)bh * SEQ * DEPTH;

    // Load Q tile transposed + fold in 1/sqrt(depth)
    #pragma unroll
    for (int it = 0; it < 4; ++it) {
        const int idx = tid + it * 256;
        const int r = idx >> 4;
        const int d = (idx & 15) << 2;
        float4 v = *(const float4*)(qg + r * DEPTH + d);
        Qt[(d+0)*68 + r] = v.x * 0.125f;
        Qt[(d+1)*68 + r] = v.y * 0.125f;
        Qt[(d+2)*68 + r] = v.z * 0.125f;
        Qt[(d+3)*68 + r] = v.w * 0.125f;
    }

    float O[4][4];
    float mrun[4], lrun[4];
    #pragma unroll
    for (int i = 0; i < 4; ++i) {
        mrun[i] = -1e30f;
        lrun[i] = 0.f;
        #pragma unroll
        for (int c = 0; c < 4; ++c) O[i][c] = 0.f;
    }

    for (int kt = 0; kt < SEQ / 64; ++kt) {
        __syncthreads();   // prior PV done before K/V/P overwrites
        const float* kg = kgb + kt * 64 * DEPTH;
        const float* vg = vgb + kt * 64 * DEPTH;
        #pragma unroll
        for (int it = 0; it < 4; ++it) {
            const int idx = tid + it * 256;
            const int r = idx >> 4;
            const int d = (idx & 15) << 2;
            float4 kv = *(const float4*)(kg + r * DEPTH + d);
            Kt[(d+0)*68 + r] = kv.x;
            Kt[(d+1)*68 + r] = kv.y;
            Kt[(d+2)*68 + r] = kv.z;
            Kt[(d+3)*68 + r] = kv.w;
            *(float4*)(Vs + r * 68 + d) = *(const float4*)(vg + r * DEPTH + d);
        }
        __syncthreads();

        // S = (Q/8) @ K^T  (4x4 per thread)
        float sacc[4][4];
        #pragma unroll
        for (int i = 0; i < 4; ++i)
            #pragma unroll
            for (int j = 0; j < 4; ++j) sacc[i][j] = 0.f;
        #pragma unroll 8
        for (int d = 0; d < 64; ++d) {
            float4 a = *(const float4*)(Qt + d * 68 + ty * 4);
            float4 b = *(const float4*)(Kt + d * 68 + tx * 4);
            float av[4] = {a.x, a.y, a.z, a.w};
            float bv[4] = {b.x, b.y, b.z, b.w};
            #pragma unroll
            for (int i = 0; i < 4; ++i)
                #pragma unroll
                for (int j = 0; j < 4; ++j)
                    sacc[i][j] = fmaf(av[i], bv[j], sacc[i][j]);
        }

        // Online softmax (rows live in one 16-lane half-warp: shuffle xor 1,2,4,8)
        float mloc[4];
        #pragma unroll
        for (int i = 0; i < 4; ++i) {
            mloc[i] = fmaxf(fmaxf(sacc[i][0], sacc[i][1]), fmaxf(sacc[i][2], sacc[i][3]));
        }
        #pragma unroll
        for (int off = 1; off < 16; off <<= 1)
            #pragma unroll
            for (int i = 0; i < 4; ++i)
                mloc[i] = fmaxf(mloc[i], __shfl_xor_sync(0xffffffffu, mloc[i], off));

        float alpha[4], rs[4];
        #pragma unroll
        for (int i = 0; i < 4; ++i) {
            const float mn = fmaxf(mrun[i], mloc[i]);
            alpha[i] = __expf(mrun[i] - mn);
            mrun[i]  = mn;
            float s = 0.f;
            #pragma unroll
            for (int j = 0; j < 4; ++j) {
                const float p = __expf(sacc[i][j] - mn);
                sacc[i][j] = p;
                s += p;
            }
            rs[i] = s;
        }
        #pragma unroll
        for (int off = 1; off < 16; off <<= 1)
            #pragma unroll
            for (int i = 0; i < 4; ++i)
                rs[i] += __shfl_xor_sync(0xffffffffu, rs[i], off);
        #pragma unroll
        for (int i = 0; i < 4; ++i) {
            lrun[i] = lrun[i] * alpha[i] + rs[i];
            #pragma unroll
            for (int c = 0; c < 4; ++c) O[i][c] *= alpha[i];
        }

        // P -> smem (key-major)
        #pragma unroll
        for (int i = 0; i < 4; ++i)
            #pragma unroll
            for (int j = 0; j < 4; ++j)
                Pt[(tx * 4 + j) * 68 + (ty * 4 + i)] = sacc[i][j];
        __syncthreads();

        // O += P @ V
        #pragma unroll 8
        for (int j = 0; j < 64; ++j) {
            float4 p = *(const float4*)(Pt + j * 68 + ty * 4);
            float4 v = *(const float4*)(Vs + j * 68 + tx * 4);
            float pv[4] = {p.x, p.y, p.z, p.w};
            float vv[4] = {v.x, v.y, v.z, v.w};
            #pragma unroll
            for (int i = 0; i < 4; ++i)
                #pragma unroll
                for (int c = 0; c < 4; ++c)
                    O[i][c] = fmaf(pv[i], vv[c], O[i][c]);
        }
    }

    // Normalize, write to [B,S,1024]
    const int bb = bh >> 4;
    const int h  = bh & 15;
    #pragma unroll
    for (int i = 0; i < 4; ++i) {
        const float inv = 1.0f / lrun[i];
        const int s = q0 + ty * 4 + i;
        float4 o4 = make_float4(O[i][0] * inv, O[i][1] * inv, O[i][2] * inv, O[i][3] * inv);
        *(float4*)(g_att + ((size_t)bb * SEQ + s) * DM + h * DEPTH + tx * 4) = o4;
    }
}

// ---------------------------------------------------------------------------
// Final projection: out = att @ Wf^T, plain [8192,1024] output
// ---------------------------------------------------------------------------
__global__ __launch_bounds__(256) void proj_out_kernel(const float* __restrict__ wf,
                                                       float* __restrict__ out) {
    float acc[8][8];
    #pragma unroll
    for (int i = 0; i < 8; ++i)
        #pragma unroll
        for (int j = 0; j < 8; ++j) acc[i][j] = 0.f;

    const int m0 = blockIdx.y * 128;
    const int n0 = blockIdx.x * 128;
    gemm_block(g_att, wf, m0, n0, acc);

    const int ty = threadIdx.x >> 4;
    const int tx = threadIdx.x & 15;
    #pragma unroll
    for (int i = 0; i < 8; ++i) {
        const int m = m0 + ty * 8 + i;
        #pragma unroll
        for (int jq = 0; jq < 8; jq += 4) {
            const int n = n0 + tx * 8 + jq;
            *(float4*)(out + (size_t)m * DM + n) =
                make_float4(acc[i][jq], acc[i][jq+1], acc[i][jq+2], acc[i][jq+3]);
        }
    }
}

// ---------------------------------------------------------------------------
extern "C" void kernel_launch(void* const* d_in, const int* in_sizes, int n_in,
                              void* d_out, int out_size) {
    const float* x  = (const float*)d_in[0];
    const float* wq = (const float*)d_in[1];
    const float* wk = (const float*)d_in[2];
    const float* wv = (const float*)d_in[3];
    const float* wf = (const float*)d_in[4];
    float* out = (float*)d_out;

    const int attn_smem = 4 * 64 * 68 * (int)sizeof(float);  // 69632 B
    cudaFuncSetAttribute(attn_kernel, cudaFuncAttributeMaxDynamicSharedMemorySize, attn_smem);

    dim3 g1(DM / 128, MTOT / 128, 3);      // (8, 64, 3)
    proj_qkv_kernel<<<g1, 256>>>(x, wq, wk, wv);

    dim3 g2(SEQ / 64, BATCH * NHEAD);      // (32, 64)
    attn_kernel<<<g2, 256, attn_smem>>>();

    dim3 g3(DM / 128, MTOT / 128);         // (8, 64)
    proj_out_kernel<<<g3, 256>>>(wf, out);
}

// round 3
// speedup vs baseline: 1.3463x; 1.3463x over previous
#include <cuda_runtime.h>
#include <cuda_bf16.h>
#include <cstdint>

#define DM      1024
#define NHEAD   16
#define DEPTH   64
#define BATCH   4
#define SEQ     2048
#define MTOT    (BATCH*SEQ)   // 8192

// ---------------------------------------------------------------------------
// Device-global scratch (no dynamic allocation allowed)
// ---------------------------------------------------------------------------
__device__ float g_q[BATCH*NHEAD*SEQ*DEPTH];    // [B,H,S,64] fp32
__device__ float g_k[BATCH*NHEAD*SEQ*DEPTH];
__device__ float g_v[BATCH*NHEAD*SEQ*DEPTH];
__device__ float g_att[BATCH*SEQ*DM];           // [B,S,1024] fp32

__device__ __nv_bfloat16 g_xh[MTOT*DM], g_xl[MTOT*DM];   // x split
__device__ __nv_bfloat16 g_wh[4][DM*DM], g_wl[4][DM*DM]; // wq,wk,wv,wf split
__device__ __nv_bfloat16 g_ah[MTOT*DM], g_al[MTOT*DM];   // att split

// ---------------------------------------------------------------------------
// MMA helpers (base-ISA: valid on plain sm_103 target)
// ---------------------------------------------------------------------------
__device__ __forceinline__ uint32_t smem_u32(const void* p) {
    uint32_t a;
    asm("{ .reg .u64 t; cvta.to.shared.u64 t, %1; cvt.u32.u64 %0, t; }" : "=r"(a) : "l"(p));
    return a;
}

__device__ __forceinline__ void mma_bf16(float d[4], const uint32_t a[4], const uint32_t b[2]) {
    asm volatile(
        "mma.sync.aligned.m16n8k16.row.col.f32.bf16.bf16.f32 "
        "{%0,%1,%2,%3}, {%4,%5,%6,%7}, {%8,%9}, {%0,%1,%2,%3};\n"
        : "+f"(d[0]), "+f"(d[1]), "+f"(d[2]), "+f"(d[3])
        : "r"(a[0]), "r"(a[1]), "r"(a[2]), "r"(a[3]), "r"(b[0]), "r"(b[1]));
}
__device__ __forceinline__ void ldsm_x4(uint32_t r[4], uint32_t addr) {
    asm volatile("ldmatrix.sync.aligned.m8n8.x4.shared.b16 {%0,%1,%2,%3}, [%4];"
        : "=r"(r[0]), "=r"(r[1]), "=r"(r[2]), "=r"(r[3]) : "r"(addr));
}
__device__ __forceinline__ void ldsm_x2(uint32_t r[2], uint32_t addr) {
    asm volatile("ldmatrix.sync.aligned.m8n8.x2.shared.b16 {%0,%1}, [%2];"
        : "=r"(r[0]), "=r"(r[1]) : "r"(addr));
}

// ---------------------------------------------------------------------------
// Split fp32 -> (bf16 hi, bf16 lo).  sel: 0=x, 1..4=wq/wk/wv/wf, 5=g_att
// ---------------------------------------------------------------------------
__global__ __launch_bounds__(256) void split_kernel(const float* __restrict__ in, int sel, int n4) {
    int i = blockIdx.x * 256 + threadIdx.x;
    if (i >= n4) return;
    const float* src = in;
    __nv_bfloat16 *hi, *lo;
    if (sel == 0)      { hi = g_xh;        lo = g_xl; }
    else if (sel <= 4) { hi = g_wh[sel-1]; lo = g_wl[sel-1]; }
    else               { hi = g_ah;        lo = g_al;        src = g_att; }

    float4 v = ((const float4*)src)[i];
    __nv_bfloat16 h0 = __float2bfloat16(v.x);
    __nv_bfloat16 h1 = __float2bfloat16(v.y);
    __nv_bfloat16 h2 = __float2bfloat16(v.z);
    __nv_bfloat16 h3 = __float2bfloat16(v.w);
    __nv_bfloat16 l0 = __float2bfloat16(v.x - __bfloat162float(h0));
    __nv_bfloat16 l1 = __float2bfloat16(v.y - __bfloat162float(h1));
    __nv_bfloat16 l2 = __float2bfloat16(v.z - __bfloat162float(h2));
    __nv_bfloat16 l3 = __float2bfloat16(v.w - __bfloat162float(h3));
    ((__nv_bfloat162*)hi)[i*2 + 0] = __halves2bfloat162(h0, h1);
    ((__nv_bfloat162*)hi)[i*2 + 1] = __halves2bfloat162(h2, h3);
    ((__nv_bfloat162*)lo)[i*2 + 0] = __halves2bfloat162(l0, l1);
    ((__nv_bfloat162*)lo)[i*2 + 1] = __halves2bfloat162(l2, l3);
}

// ---------------------------------------------------------------------------
// HMMA tile GEMM: C(128x128) = A[128,1024] * W[128,1024]^T via split bf16.
// 256 threads = 8 warps in 2(M) x 4(N); warp tile 64x32; K chunk 32,
// double-buffered SMEM; rows padded to 80B for conflict-free ldmatrix.
//
// SMEM stage layout (40960 B): Ah @0, Al @10240, Wh @20480, Wl @30720
// each array: 128 rows x 80 B (32 bf16 data + 8 pad). 2 stages = 81920 B.
// ---------------------------------------------------------------------------
#define STAGE_BYTES 40960
#define GEMM_SMEM_BYTES (2*STAGE_BYTES)

__device__ __forceinline__ void ldg_chunk(const __nv_bfloat16* __restrict__ Ah,
                                          const __nv_bfloat16* __restrict__ Al,
                                          const __nv_bfloat16* __restrict__ Wh,
                                          const __nv_bfloat16* __restrict__ Wl,
                                          int m0, int n0, int k0, int tid, uint4 r[8]) {
    const int row = tid >> 1;
    const int u0  = (tid & 1) * 2;            // 16B unit index 0 or 2
    const size_t ka = (size_t)(m0 + row) * DM + k0 + u0 * 8;
    const size_t kb = (size_t)(n0 + row) * DM + k0 + u0 * 8;
    r[0] = *(const uint4*)(Ah + ka);  r[1] = *(const uint4*)(Ah + ka + 8);
    r[2] = *(const uint4*)(Al + ka);  r[3] = *(const uint4*)(Al + ka + 8);
    r[4] = *(const uint4*)(Wh + kb);  r[5] = *(const uint4*)(Wh + kb + 8);
    r[6] = *(const uint4*)(Wl + kb);  r[7] = *(const uint4*)(Wl + kb + 8);
}

__device__ __forceinline__ void sts_chunk(char* sm, int stage, int tid, const uint4 r[8]) {
    char* base = sm + stage * STAGE_BYTES;
    const int row = tid >> 1;
    const int u0  = (tid & 1) * 2;
    const int o   = row * 80 + u0 * 16;
    *(uint4*)(base + o)              = r[0];  *(uint4*)(base + o + 16)          = r[1];
    *(uint4*)(base + 10240 + o)      = r[2];  *(uint4*)(base + 10240 + o + 16)  = r[3];
    *(uint4*)(base + 20480 + o)      = r[4];  *(uint4*)(base + 20480 + o + 16)  = r[5];
    *(uint4*)(base + 30720 + o)      = r[6];  *(uint4*)(base + 30720 + o + 16)  = r[7];
}

__device__ __forceinline__ void run_tile_mma(const __nv_bfloat16* __restrict__ Ah,
                                             const __nv_bfloat16* __restrict__ Al,
                                             const __nv_bfloat16* __restrict__ Wh,
                                             const __nv_bfloat16* __restrict__ Wl,
                                             int m0, int n0, char* smptr,
                                             float acc[4][4][4]) {
    const int tid  = threadIdx.x;
    const int wid  = tid >> 5;
    const int lane = tid & 31;
    const int wm   = wid >> 2;       // 0..1
    const int wn   = wid & 3;        // 0..3
    const uint32_t sb = smem_u32(smptr);

    // fragment smem addressing (byte offsets, stage-relative)
    const uint32_t a_row = (uint32_t)(wm * 64 + (lane & 15));
    const uint32_t a_col = (uint32_t)((lane >> 4) * 16);
    const uint32_t b_row = (uint32_t)(wn * 32 + (lane & 7));
    const uint32_t b_col = (uint32_t)(((lane >> 3) & 1) * 16);

    uint4 r[8], rn[8];
    ldg_chunk(Ah, Al, Wh, Wl, m0, n0, 0, tid, r);
    sts_chunk(smptr, 0, tid, r);
    __syncthreads();

    #pragma unroll 1
    for (int c = 0; c < 32; ++c) {
        const int cur = c & 1;
        if (c < 31) ldg_chunk(Ah, Al, Wh, Wl, m0, n0, (c + 1) * 32, tid, rn);
        const uint32_t st = sb + cur * STAGE_BYTES;
        #pragma unroll
        for (int ks = 0; ks < 2; ++ks) {
            uint32_t ah[4][4], alr[4][4], bh[4][2], bl[4][2];
            #pragma unroll
            for (int mt = 0; mt < 4; ++mt) {
                const uint32_t ad = st + (a_row + mt * 16) * 80 + ks * 32 + a_col;
                ldsm_x4(ah[mt], ad);
                ldsm_x4(alr[mt], ad + 10240);
            }
            #pragma unroll
            for (int nt = 0; nt < 4; ++nt) {
                const uint32_t bd = st + 20480 + (b_row + nt * 8) * 80 + ks * 32 + b_col;
                ldsm_x2(bh[nt], bd);
                ldsm_x2(bl[nt], bd + 10240);
            }
            #pragma unroll
            for (int mt = 0; mt < 4; ++mt)
                #pragma unroll
                for (int nt = 0; nt < 4; ++nt) {
                    mma_bf16(acc[mt][nt], ah[mt],  bh[nt]);
                    mma_bf16(acc[mt][nt], ah[mt],  bl[nt]);
                    mma_bf16(acc[mt][nt], alr[mt], bh[nt]);
                }
        }
        if (c < 31) {
            sts_chunk(smptr, cur ^ 1, tid, rn);
            __syncthreads();
        }
    }
}

// ---------------------------------------------------------------------------
// QKV projection: grid (8, 64, 3); scatter epilogue to g_q/g_k/g_v [B,H,S,64]
// ---------------------------------------------------------------------------
__global__ __launch_bounds__(256, 1) void gemm_qkv_mma() {
    extern __shared__ char smem[];
    const int z  = blockIdx.z;
    const int m0 = blockIdx.y * 128;
    const int n0 = blockIdx.x * 128;

    float acc[4][4][4];
    #pragma unroll
    for (int a = 0; a < 4; ++a)
        #pragma unroll
        for (int b = 0; b < 4; ++b)
            #pragma unroll
            for (int cc = 0; cc < 4; ++cc) acc[a][b][cc] = 0.f;

    run_tile_mma(g_xh, g_xl, g_wh[z], g_wl[z], m0, n0, smem, acc);

    float* outb = (z == 0) ? g_q : (z == 1) ? g_k : g_v;
    const int wid  = threadIdx.x >> 5;
    const int lane = threadIdx.x & 31;
    const int wm   = wid >> 2;
    const int wn   = wid & 3;

    #pragma unroll
    for (int mt = 0; mt < 4; ++mt) {
        #pragma unroll
        for (int nt = 0; nt < 4; ++nt) {
            const int col = n0 + wn * 32 + nt * 8 + (lane & 3) * 2;
            const int h   = col >> 6;
            const int dd  = col & 63;
            #pragma unroll
            for (int half = 0; half < 2; ++half) {
                const int row = m0 + wm * 64 + mt * 16 + (lane >> 2) + half * 8;
                const int bb  = row >> 11;
                const int ss  = row & 2047;
                float* dst = outb + ((((size_t)bb * NHEAD + h) * SEQ + ss) * DEPTH + dd);
                *(float2*)dst = make_float2(acc[mt][nt][half * 2], acc[mt][nt][half * 2 + 1]);
            }
        }
    }
}

// ---------------------------------------------------------------------------
// Output projection: grid (8, 64); plain [8192,1024] epilogue
// ---------------------------------------------------------------------------
__global__ __launch_bounds__(256, 1) void gemm_out_mma(float* __restrict__ out) {
    extern __shared__ char smem[];
    const int m0 = blockIdx.y * 128;
    const int n0 = blockIdx.x * 128;

    float acc[4][4][4];
    #pragma unroll
    for (int a = 0; a < 4; ++a)
        #pragma unroll
        for (int b = 0; b < 4; ++b)
            #pragma unroll
            for (int cc = 0; cc < 4; ++cc) acc[a][b][cc] = 0.f;

    run_tile_mma(g_ah, g_al, g_wh[3], g_wl[3], m0, n0, smem, acc);

    const int wid  = threadIdx.x >> 5;
    const int lane = threadIdx.x & 31;
    const int wm   = wid >> 2;
    const int wn   = wid & 3;

    #pragma unroll
    for (int mt = 0; mt < 4; ++mt) {
        #pragma unroll
        for (int nt = 0; nt < 4; ++nt) {
            const int col = n0 + wn * 32 + nt * 8 + (lane & 3) * 2;
            #pragma unroll
            for (int half = 0; half < 2; ++half) {
                const int row = m0 + wm * 64 + mt * 16 + (lane >> 2) + half * 8;
                *(float2*)(out + (size_t)row * DM + col) =
                    make_float2(acc[mt][nt][half * 2], acc[mt][nt][half * 2 + 1]);
            }
        }
    }
}

// ---------------------------------------------------------------------------
// Flash attention (unchanged fp32 SIMT): per (b,h), 64-query tiles x 2048 keys
// ---------------------------------------------------------------------------
__global__ __launch_bounds__(256) void attn_kernel() {
    extern __shared__ float sm[];
    float* Qt = sm;
    float* Kt = Qt + 64 * 68;
    float* Vs = Kt + 64 * 68;
    float* Pt = Vs + 64 * 68;

    const int tid = threadIdx.x;
    const int ty  = tid >> 4;
    const int tx  = tid & 15;
    const int bh  = blockIdx.y;
    const int q0  = blockIdx.x * 64;

    const float* qg  = g_q + ((size_t)bh * SEQ + q0) * DEPTH;
    const float* kgb = g_k + (size_t)bh * SEQ * DEPTH;
    const float* vgb = g_v + (size_t)bh * SEQ * DEPTH;

    #pragma unroll
    for (int it = 0; it < 4; ++it) {
        const int idx = tid + it * 256;
        const int r = idx >> 4;
        const int d = (idx & 15) << 2;
        float4 v = *(const float4*)(qg + r * DEPTH + d);
        Qt[(d+0)*68 + r] = v.x * 0.125f;
        Qt[(d+1)*68 + r] = v.y * 0.125f;
        Qt[(d+2)*68 + r] = v.z * 0.125f;
        Qt[(d+3)*68 + r] = v.w * 0.125f;
    }

    float O[4][4];
    float mrun[4], lrun[4];
    #pragma unroll
    for (int i = 0; i < 4; ++i) {
        mrun[i] = -1e30f; lrun[i] = 0.f;
        #pragma unroll
        for (int c = 0; c < 4; ++c) O[i][c] = 0.f;
    }

    for (int kt = 0; kt < SEQ / 64; ++kt) {
        __syncthreads();
        const float* kg = kgb + kt * 64 * DEPTH;
        const float* vg = vgb + kt * 64 * DEPTH;
        #pragma unroll
        for (int it = 0; it < 4; ++it) {
            const int idx = tid + it * 256;
            const int r = idx >> 4;
            const int d = (idx & 15) << 2;
            float4 kv = *(const float4*)(kg + r * DEPTH + d);
            Kt[(d+0)*68 + r] = kv.x;
            Kt[(d+1)*68 + r] = kv.y;
            Kt[(d+2)*68 + r] = kv.z;
            Kt[(d+3)*68 + r] = kv.w;
            *(float4*)(Vs + r * 68 + d) = *(const float4*)(vg + r * DEPTH + d);
        }
        __syncthreads();

        float sacc[4][4];
        #pragma unroll
        for (int i = 0; i < 4; ++i)
            #pragma unroll
            for (int j = 0; j < 4; ++j) sacc[i][j] = 0.f;
        #pragma unroll 8
        for (int d = 0; d < 64; ++d) {
            float4 a = *(const float4*)(Qt + d * 68 + ty * 4);
            float4 b = *(const float4*)(Kt + d * 68 + tx * 4);
            float av[4] = {a.x, a.y, a.z, a.w};
            float bv[4] = {b.x, b.y, b.z, b.w};
            #pragma unroll
            for (int i = 0; i < 4; ++i)
                #pragma unroll
                for (int j = 0; j < 4; ++j)
                    sacc[i][j] = fmaf(av[i], bv[j], sacc[i][j]);
        }

        float mloc[4];
        #pragma unroll
        for (int i = 0; i < 4; ++i)
            mloc[i] = fmaxf(fmaxf(sacc[i][0], sacc[i][1]), fmaxf(sacc[i][2], sacc[i][3]));
        #pragma unroll
        for (int off = 1; off < 16; off <<= 1)
            #pragma unroll
            for (int i = 0; i < 4; ++i)
                mloc[i] = fmaxf(mloc[i], __shfl_xor_sync(0xffffffffu, mloc[i], off));

        float alpha[4], rs[4];
        #pragma unroll
        for (int i = 0; i < 4; ++i) {
            const float mn = fmaxf(mrun[i], mloc[i]);
            alpha[i] = __expf(mrun[i] - mn);
            mrun[i]  = mn;
            float s = 0.f;
            #pragma unroll
            for (int j = 0; j < 4; ++j) {
                const float p = __expf(sacc[i][j] - mn);
                sacc[i][j] = p;
                s += p;
            }
            rs[i] = s;
        }
        #pragma unroll
        for (int off = 1; off < 16; off <<= 1)
            #pragma unroll
            for (int i = 0; i < 4; ++i)
                rs[i] += __shfl_xor_sync(0xffffffffu, rs[i], off);
        #pragma unroll
        for (int i = 0; i < 4; ++i) {
            lrun[i] = lrun[i] * alpha[i] + rs[i];
            #pragma unroll
            for (int c = 0; c < 4; ++c) O[i][c] *= alpha[i];
        }

        #pragma unroll
        for (int i = 0; i < 4; ++i)
            #pragma unroll
            for (int j = 0; j < 4; ++j)
                Pt[(tx * 4 + j) * 68 + (ty * 4 + i)] = sacc[i][j];
        __syncthreads();

        #pragma unroll 8
        for (int j = 0; j < 64; ++j) {
            float4 p = *(const float4*)(Pt + j * 68 + ty * 4);
            float4 v = *(const float4*)(Vs + j * 68 + tx * 4);
            float pv[4] = {p.x, p.y, p.z, p.w};
            float vv[4] = {v.x, v.y, v.z, v.w};
            #pragma unroll
            for (int i = 0; i < 4; ++i)
                #pragma unroll
                for (int c = 0; c < 4; ++c)
                    O[i][c] = fmaf(pv[i], vv[c], O[i][c]);
        }
    }

    const int bb = bh >> 4;
    const int h  = bh & 15;
    #pragma unroll
    for (int i = 0; i < 4; ++i) {
        const float inv = 1.0f / lrun[i];
        const int s = q0 + ty * 4 + i;
        float4 o4 = make_float4(O[i][0] * inv, O[i][1] * inv, O[i][2] * inv, O[i][3] * inv);
        *(float4*)(g_att + ((size_t)bb * SEQ + s) * DM + h * DEPTH + tx * 4) = o4;
    }
}

// ---------------------------------------------------------------------------
extern "C" void kernel_launch(void* const* d_in, const int* in_sizes, int n_in,
                              void* d_out, int out_size) {
    const float* x  = (const float*)d_in[0];
    const float* wq = (const float*)d_in[1];
    const float* wk = (const float*)d_in[2];
    const float* wv = (const float*)d_in[3];
    const float* wf = (const float*)d_in[4];
    float* out = (float*)d_out;

    const int attn_smem = 4 * 64 * 68 * (int)sizeof(float);  // 69632 B
    cudaFuncSetAttribute(attn_kernel, cudaFuncAttributeMaxDynamicSharedMemorySize, attn_smem);
    cudaFuncSetAttribute(gemm_qkv_mma, cudaFuncAttributeMaxDynamicSharedMemorySize, GEMM_SMEM_BYTES);
    cudaFuncSetAttribute(gemm_out_mma, cudaFuncAttributeMaxDynamicSharedMemorySize, GEMM_SMEM_BYTES);

    // Split conversions
    split_kernel<<<MTOT * DM / 4 / 256, 256>>>(x,  0, MTOT * DM / 4);
    split_kernel<<<DM * DM / 4 / 256,   256>>>(wq, 1, DM * DM / 4);
    split_kernel<<<DM * DM / 4 / 256,   256>>>(wk, 2, DM * DM / 4);
    split_kernel<<<DM * DM / 4 / 256,   256>>>(wv, 3, DM * DM / 4);
    split_kernel<<<DM * DM / 4 / 256,   256>>>(wf, 4, DM * DM / 4);

    // QKV projection (HMMA)
    dim3 g1(DM / 128, MTOT / 128, 3);
    gemm_qkv_mma<<<g1, 256, GEMM_SMEM_BYTES>>>();

    // Attention (fp32 SIMT)
    dim3 g2(SEQ / 64, BATCH * NHEAD);
    attn_kernel<<<g2, 256, attn_smem>>>();

    // Split attention output, final projection (HMMA)
    split_kernel<<<MTOT * DM / 4 / 256, 256>>>(nullptr, 5, MTOT * DM / 4);
    dim3 g3(DM / 128, MTOT / 128);
    gemm_out_mma<<<g3, 256, GEMM_SMEM_BYTES>>>(out);
}

// round 4
// speedup vs baseline: 3.1774x; 2.3600x over previous
#include <cuda_runtime.h>
#include <cuda_bf16.h>
#include <cuda_fp16.h>
#include <cstdint>

#define DM      1024
#define NHEAD   16
#define DEPTH   64
#define BATCH   4
#define SEQ     2048
#define MTOT    (BATCH*SEQ)   // 8192
#define NBH     (BATCH*NHEAD) // 64

// ---------------------------------------------------------------------------
// Device-global scratch
// ---------------------------------------------------------------------------
__device__ __nv_bfloat16 g_qh[NBH*SEQ*DEPTH], g_ql[NBH*SEQ*DEPTH]; // Q/8 split
__device__ __nv_bfloat16 g_kh[NBH*SEQ*DEPTH], g_kl[NBH*SEQ*DEPTH]; // K split
__device__ __half        g_vh[NBH*SEQ*DEPTH];                      // V fp16
__device__ __nv_bfloat16 g_ah[MTOT*DM], g_al[MTOT*DM];             // attn out split
__device__ __nv_bfloat16 g_xh[MTOT*DM], g_xl[MTOT*DM];             // x split
__device__ __nv_bfloat16 g_wh[4][DM*DM], g_wl[4][DM*DM];           // weights split

// ---------------------------------------------------------------------------
// PTX helpers (base ISA only: valid on plain sm_103 target)
// ---------------------------------------------------------------------------
__device__ __forceinline__ uint32_t smem_u32(const void* p) {
    uint32_t a;
    asm("{ .reg .u64 t; cvta.to.shared.u64 t, %1; cvt.u32.u64 %0, t; }" : "=r"(a) : "l"(p));
    return a;
}
__device__ __forceinline__ void mma_bf16(float d[4], const uint32_t a[4], const uint32_t b[2]) {
    asm volatile(
        "mma.sync.aligned.m16n8k16.row.col.f32.bf16.bf16.f32 "
        "{%0,%1,%2,%3}, {%4,%5,%6,%7}, {%8,%9}, {%0,%1,%2,%3};\n"
        : "+f"(d[0]), "+f"(d[1]), "+f"(d[2]), "+f"(d[3])
        : "r"(a[0]), "r"(a[1]), "r"(a[2]), "r"(a[3]), "r"(b[0]), "r"(b[1]));
}
__device__ __forceinline__ void mma_f16(float d[4], const uint32_t a[4], const uint32_t b[2]) {
    asm volatile(
        "mma.sync.aligned.m16n8k16.row.col.f32.f16.f16.f32 "
        "{%0,%1,%2,%3}, {%4,%5,%6,%7}, {%8,%9}, {%0,%1,%2,%3};\n"
        : "+f"(d[0]), "+f"(d[1]), "+f"(d[2]), "+f"(d[3])
        : "r"(a[0]), "r"(a[1]), "r"(a[2]), "r"(a[3]), "r"(b[0]), "r"(b[1]));
}
__device__ __forceinline__ void ldsm_x4(uint32_t r[4], uint32_t addr) {
    asm volatile("ldmatrix.sync.aligned.m8n8.x4.shared.b16 {%0,%1,%2,%3}, [%4];"
        : "=r"(r[0]), "=r"(r[1]), "=r"(r[2]), "=r"(r[3]) : "r"(addr));
}
__device__ __forceinline__ void ldsm_x2(uint32_t r[2], uint32_t addr) {
    asm volatile("ldmatrix.sync.aligned.m8n8.x2.shared.b16 {%0,%1}, [%2];"
        : "=r"(r[0]), "=r"(r[1]) : "r"(addr));
}
__device__ __forceinline__ void ldsm_x2t(uint32_t r[2], uint32_t addr) {
    asm volatile("ldmatrix.sync.aligned.m8n8.x2.trans.shared.b16 {%0,%1}, [%2];"
        : "=r"(r[0]), "=r"(r[1]) : "r"(addr));
}
__device__ __forceinline__ void cp16(uint32_t saddr, const void* g) {
    asm volatile("cp.async.cg.shared.global [%0], [%1], 16;" :: "r"(saddr), "l"(g));
}
#define CP_COMMIT() asm volatile("cp.async.commit_group;" ::: "memory")
#define CP_WAIT1()  asm volatile("cp.async.wait_group 1;"  ::: "memory")
#define CP_WAIT0()  asm volatile("cp.async.wait_group 0;"  ::: "memory")

__device__ __forceinline__ uint32_t pack_h2(float x, float y) {
    __half2 h = __floats2half2_rn(x, y);
    return *(uint32_t*)&h;
}
__device__ __forceinline__ void split_store(__nv_bfloat16* hi, __nv_bfloat16* lo,
                                            size_t idx, float v0, float v1) {
    __nv_bfloat16 h0 = __float2bfloat16(v0);
    __nv_bfloat16 h1 = __float2bfloat16(v1);
    __nv_bfloat16 e0 = __float2bfloat16(v0 - __bfloat162float(h0));
    __nv_bfloat16 e1 = __float2bfloat16(v1 - __bfloat162float(h1));
    *(__nv_bfloat162*)(hi + idx) = __halves2bfloat162(h0, h1);
    *(__nv_bfloat162*)(lo + idx) = __halves2bfloat162(e0, e1);
}

// ---------------------------------------------------------------------------
// Split fp32 -> (bf16 hi, bf16 lo).  sel: 0=x, 1..4=wq/wk/wv/wf
// ---------------------------------------------------------------------------
__global__ __launch_bounds__(256) void split_kernel(const float* __restrict__ in, int sel, int n4) {
    int i = blockIdx.x * 256 + threadIdx.x;
    if (i >= n4) return;
    __nv_bfloat16 *hi, *lo;
    if (sel == 0) { hi = g_xh;        lo = g_xl; }
    else          { hi = g_wh[sel-1]; lo = g_wl[sel-1]; }

    float4 v = ((const float4*)in)[i];
    __nv_bfloat16 h0 = __float2bfloat16(v.x);
    __nv_bfloat16 h1 = __float2bfloat16(v.y);
    __nv_bfloat16 h2 = __float2bfloat16(v.z);
    __nv_bfloat16 h3 = __float2bfloat16(v.w);
    __nv_bfloat16 l0 = __float2bfloat16(v.x - __bfloat162float(h0));
    __nv_bfloat16 l1 = __float2bfloat16(v.y - __bfloat162float(h1));
    __nv_bfloat16 l2 = __float2bfloat16(v.z - __bfloat162float(h2));
    __nv_bfloat16 l3 = __float2bfloat16(v.w - __bfloat162float(h3));
    ((__nv_bfloat162*)hi)[i*2 + 0] = __halves2bfloat162(h0, h1);
    ((__nv_bfloat162*)hi)[i*2 + 1] = __halves2bfloat162(h2, h3);
    ((__nv_bfloat162*)lo)[i*2 + 0] = __halves2bfloat162(l0, l1);
    ((__nv_bfloat162*)lo)[i*2 + 1] = __halves2bfloat162(l2, l3);
}

// ---------------------------------------------------------------------------
// HMMA tile GEMM machinery (unchanged from round 3)
// ---------------------------------------------------------------------------
#define STAGE_BYTES 40960
#define GEMM_SMEM_BYTES (2*STAGE_BYTES)

__device__ __forceinline__ void ldg_chunk(const __nv_bfloat16* __restrict__ Ah,
                                          const __nv_bfloat16* __restrict__ Al,
                                          const __nv_bfloat16* __restrict__ Wh,
                                          const __nv_bfloat16* __restrict__ Wl,
                                          int m0, int n0, int k0, int tid, uint4 r[8]) {
    const int row = tid >> 1;
    const int u0  = (tid & 1) * 2;
    const size_t ka = (size_t)(m0 + row) * DM + k0 + u0 * 8;
    const size_t kb = (size_t)(n0 + row) * DM + k0 + u0 * 8;
    r[0] = *(const uint4*)(Ah + ka);  r[1] = *(const uint4*)(Ah + ka + 8);
    r[2] = *(const uint4*)(Al + ka);  r[3] = *(const uint4*)(Al + ka + 8);
    r[4] = *(const uint4*)(Wh + kb);  r[5] = *(const uint4*)(Wh + kb + 8);
    r[6] = *(const uint4*)(Wl + kb);  r[7] = *(const uint4*)(Wl + kb + 8);
}

__device__ __forceinline__ void sts_chunk(char* sm, int stage, int tid, const uint4 r[8]) {
    char* base = sm + stage * STAGE_BYTES;
    const int row = tid >> 1;
    const int u0  = (tid & 1) * 2;
    const int o   = row * 80 + u0 * 16;
    *(uint4*)(base + o)              = r[0];  *(uint4*)(base + o + 16)          = r[1];
    *(uint4*)(base + 10240 + o)      = r[2];  *(uint4*)(base + 10240 + o + 16)  = r[3];
    *(uint4*)(base + 20480 + o)      = r[4];  *(uint4*)(base + 20480 + o + 16)  = r[5];
    *(uint4*)(base + 30720 + o)      = r[6];  *(uint4*)(base + 30720 + o + 16)  = r[7];
}

__device__ __forceinline__ void run_tile_mma(const __nv_bfloat16* __restrict__ Ah,
                                             const __nv_bfloat16* __restrict__ Al,
                                             const __nv_bfloat16* __restrict__ Wh,
                                             const __nv_bfloat16* __restrict__ Wl,
                                             int m0, int n0, char* smptr,
                                             float acc[4][4][4]) {
    const int tid  = threadIdx.x;
    const int wid  = tid >> 5;
    const int lane = tid & 31;
    const int wm   = wid >> 2;
    const int wn   = wid & 3;
    const uint32_t sb = smem_u32(smptr);

    const uint32_t a_row = (uint32_t)(wm * 64 + (lane & 15));
    const uint32_t a_col = (uint32_t)((lane >> 4) * 16);
    const uint32_t b_row = (uint32_t)(wn * 32 + (lane & 7));
    const uint32_t b_col = (uint32_t)(((lane >> 3) & 1) * 16);

    uint4 r[8], rn[8];
    ldg_chunk(Ah, Al, Wh, Wl, m0, n0, 0, tid, r);
    sts_chunk(smptr, 0, tid, r);
    __syncthreads();

    #pragma unroll 1
    for (int c = 0; c < 32; ++c) {
        const int cur = c & 1;
        if (c < 31) ldg_chunk(Ah, Al, Wh, Wl, m0, n0, (c + 1) * 32, tid, rn);
        const uint32_t st = sb + cur * STAGE_BYTES;
        #pragma unroll
        for (int ks = 0; ks < 2; ++ks) {
            uint32_t ah[4][4], alr[4][4], bh[4][2], bl[4][2];
            #pragma unroll
            for (int mt = 0; mt < 4; ++mt) {
                const uint32_t ad = st + (a_row + mt * 16) * 80 + ks * 32 + a_col;
                ldsm_x4(ah[mt], ad);
                ldsm_x4(alr[mt], ad + 10240);
            }
            #pragma unroll
            for (int nt = 0; nt < 4; ++nt) {
                const uint32_t bd = st + 20480 + (b_row + nt * 8) * 80 + ks * 32 + b_col;
                ldsm_x2(bh[nt], bd);
                ldsm_x2(bl[nt], bd + 10240);
            }
            #pragma unroll
            for (int mt = 0; mt < 4; ++mt)
                #pragma unroll
                for (int nt = 0; nt < 4; ++nt) {
                    mma_bf16(acc[mt][nt], ah[mt],  bh[nt]);
                    mma_bf16(acc[mt][nt], ah[mt],  bl[nt]);
                    mma_bf16(acc[mt][nt], alr[mt], bh[nt]);
                }
        }
        if (c < 31) {
            sts_chunk(smptr, cur ^ 1, tid, rn);
            __syncthreads();
        }
    }
}

// ---------------------------------------------------------------------------
// QKV projection: grid (8, 64, 3); epilogue writes split-bf16 Q/K, fp16 V
// ---------------------------------------------------------------------------
__global__ __launch_bounds__(256, 1) void gemm_qkv_mma() {
    extern __shared__ char smem[];
    const int z  = blockIdx.z;
    const int m0 = blockIdx.y * 128;
    const int n0 = blockIdx.x * 128;

    float acc[4][4][4];
    #pragma unroll
    for (int a = 0; a < 4; ++a)
        #pragma unroll
        for (int b = 0; b < 4; ++b)
            #pragma unroll
            for (int cc = 0; cc < 4; ++cc) acc[a][b][cc] = 0.f;

    run_tile_mma(g_xh, g_xl, g_wh[z], g_wl[z], m0, n0, smem, acc);

    const int wid  = threadIdx.x >> 5;
    const int lane = threadIdx.x & 31;
    const int wm   = wid >> 2;
    const int wn   = wid & 3;

    #pragma unroll
    for (int mt = 0; mt < 4; ++mt) {
        #pragma unroll
        for (int nt = 0; nt < 4; ++nt) {
            const int col = n0 + wn * 32 + nt * 8 + (lane & 3) * 2;
            const int h   = col >> 6;
            const int dd  = col & 63;
            #pragma unroll
            for (int half = 0; half < 2; ++half) {
                const int row = m0 + wm * 64 + mt * 16 + (lane >> 2) + half * 8;
                const int bb  = row >> 11;
                const int ss  = row & 2047;
                const size_t idx = (((size_t)bb * NHEAD + h) * SEQ + ss) * DEPTH + dd;
                float v0 = acc[mt][nt][half * 2];
                float v1 = acc[mt][nt][half * 2 + 1];
                if (z == 0) {
                    split_store(g_qh, g_ql, idx, v0 * 0.125f, v1 * 0.125f);
                } else if (z == 1) {
                    split_store(g_kh, g_kl, idx, v0, v1);
                } else {
                    *(__half2*)(g_vh + idx) = __floats2half2_rn(v0, v1);
                }
            }
        }
    }
}

// ---------------------------------------------------------------------------
// Output projection: grid (8, 64); plain [8192,1024] epilogue
// ---------------------------------------------------------------------------
__global__ __launch_bounds__(256, 1) void gemm_out_mma(float* __restrict__ out) {
    extern __shared__ char smem[];
    const int m0 = blockIdx.y * 128;
    const int n0 = blockIdx.x * 128;

    float acc[4][4][4];
    #pragma unroll
    for (int a = 0; a < 4; ++a)
        #pragma unroll
        for (int b = 0; b < 4; ++b)
            #pragma unroll
            for (int cc = 0; cc < 4; ++cc) acc[a][b][cc] = 0.f;

    run_tile_mma(g_ah, g_al, g_wh[3], g_wl[3], m0, n0, smem, acc);

    const int wid  = threadIdx.x >> 5;
    const int lane = threadIdx.x & 31;
    const int wm   = wid >> 2;
    const int wn   = wid & 3;

    #pragma unroll
    for (int mt = 0; mt < 4; ++mt) {
        #pragma unroll
        for (int nt = 0; nt < 4; ++nt) {
            const int col = n0 + wn * 32 + nt * 8 + (lane & 3) * 2;
            #pragma unroll
            for (int half = 0; half < 2; ++half) {
                const int row = m0 + wm * 64 + mt * 16 + (lane >> 2) + half * 8;
                *(float2*)(out + (size_t)row * DM + col) =
                    make_float2(acc[mt][nt][half * 2], acc[mt][nt][half * 2 + 1]);
            }
        }
    }
}

// ---------------------------------------------------------------------------
// HMMA flash attention.
// grid (SEQ/128=16, 64 bh), 256 threads = 8 warps, warp = 16 query rows.
// QK^T: split-bf16 3-pass. PV: fp16 single pass.
// SMEM: Qh[128x72]b 18432 | Ql 18432 | stage{0,1}: Kh 18432 | Kl 18432 | V 18432
// Row stride 144 B (64 elems + 8 pad) -> conflict-free ldmatrix.
// ---------------------------------------------------------------------------
#define ATT_QH    0
#define ATT_QL    18432
#define ATT_STG   36864
#define ATT_STGSZ 55296
#define ATT_KH    0
#define ATT_KL    18432
#define ATT_V     36864
#define ATT_SMEM  (ATT_STG + 2*ATT_STGSZ)   // 147456

__device__ __forceinline__ void cp_tile16(uint32_t sdst, const void* gsrc, int tid) {
    // 128 rows x 128 B data -> 1024 chunks of 16 B; smem row stride 144 B
    #pragma unroll
    for (int i = 0; i < 4; ++i) {
        const int c = tid + i * 256;
        const int row = c >> 3;
        const int col = c & 7;
        cp16(sdst + row * 144 + col * 16, (const char*)gsrc + c * 16);
    }
}
__device__ __forceinline__ void cp_stage(uint32_t sb, int buf,
                                         const __nv_bfloat16* kh, const __nv_bfloat16* kl,
                                         const __half* v, int kt, int tid) {
    const uint32_t s0 = sb + ATT_STG + buf * ATT_STGSZ;
    const size_t go = (size_t)kt * 128 * DEPTH;
    cp_tile16(s0 + ATT_KH, kh + go, tid);
    cp_tile16(s0 + ATT_KL, kl + go, tid);
    cp_tile16(s0 + ATT_V,  v  + go, tid);
}

__global__ __launch_bounds__(256, 1) void attn_mma() {
    extern __shared__ char smc[];
    const uint32_t sb = smem_u32(smc);
    const int tid  = threadIdx.x;
    const int wid  = tid >> 5;
    const int lane = tid & 31;
    const int bh   = blockIdx.y;
    const int q0   = blockIdx.x * 128;

    const size_t base = (size_t)bh * SEQ * DEPTH;
    const __nv_bfloat16* qhg = g_qh + base + (size_t)q0 * DEPTH;
    const __nv_bfloat16* qlg = g_ql + base + (size_t)q0 * DEPTH;
    const __nv_bfloat16* khg = g_kh + base;
    const __nv_bfloat16* klg = g_kl + base;
    const __half*        vg  = g_vh + base;

    // Prologue: Q + stage0 as group 0, stage1 as group 1
    cp_tile16(sb + ATT_QH, qhg, tid);
    cp_tile16(sb + ATT_QL, qlg, tid);
    cp_stage(sb, 0, khg, klg, vg, 0, tid);
    CP_COMMIT();
    cp_stage(sb, 1, khg, klg, vg, 1, tid);
    CP_COMMIT();
    CP_WAIT1();
    __syncthreads();

    // Q fragments (A, m16k64 per warp, hi + lo)
    uint32_t qh_f[4][4], ql_f[4][4];
    {
        const uint32_t qrow = (uint32_t)(wid * 16 + (lane & 15));
        const uint32_t qcol = (uint32_t)(((lane >> 4) & 1) * 16);
        #pragma unroll
        for (int ks = 0; ks < 4; ++ks) {
            const uint32_t ad = sb + ATT_QH + qrow * 144 + ks * 32 + qcol;
            ldsm_x4(qh_f[ks], ad);
            ldsm_x4(ql_f[ks], ad + (ATT_QL - ATT_QH));
        }
    }

    float acc_o[8][4];
    #pragma unroll
    for (int nt = 0; nt < 8; ++nt)
        #pragma unroll
        for (int c = 0; c < 4; ++c) acc_o[nt][c] = 0.f;
    float mr0 = -1e30f, mr1 = -1e30f, l0 = 0.f, l1 = 0.f;

    #pragma unroll 1
    for (int kt = 0; kt < 16; ++kt) {
        if (kt > 0) {
            if (kt < 15) { CP_WAIT1(); } else { CP_WAIT0(); }
            __syncthreads();
        }
        const uint32_t st = sb + ATT_STG + (kt & 1) * ATT_STGSZ;

        // ---- S = (Q/8) @ K^T, split-bf16 3-pass, fp32 accum ----
        float s[16][4];
        #pragma unroll
        for (int nt = 0; nt < 16; ++nt)
            #pragma unroll
            for (int c = 0; c < 4; ++c) s[nt][c] = 0.f;

        const uint32_t krow = (uint32_t)(lane & 7);
        const uint32_t kcol = (uint32_t)(((lane >> 3) & 1) * 16);
        #pragma unroll
        for (int ks = 0; ks < 4; ++ks) {
            #pragma unroll
            for (int nt = 0; nt < 16; ++nt) {
                const uint32_t bd = st + ATT_KH + (nt * 8 + krow) * 144 + ks * 32 + kcol;
                uint32_t bhf[2], blf[2];
                ldsm_x2(bhf, bd);
                ldsm_x2(blf, bd + (ATT_KL - ATT_KH));
                mma_bf16(s[nt], qh_f[ks], bhf);
                mma_bf16(s[nt], qh_f[ks], blf);
                mma_bf16(s[nt], ql_f[ks], bhf);
            }
        }

        // ---- online softmax (rows: r0 = lane/4, r1 = +8 within warp tile) ----
        float m0 = -1e30f, m1 = -1e30f;
        #pragma unroll
        for (int nt = 0; nt < 16; ++nt) {
            m0 = fmaxf(m0, fmaxf(s[nt][0], s[nt][1]));
            m1 = fmaxf(m1, fmaxf(s[nt][2], s[nt][3]));
        }
        m0 = fmaxf(m0, __shfl_xor_sync(0xffffffffu, m0, 1));
        m0 = fmaxf(m0, __shfl_xor_sync(0xffffffffu, m0, 2));
        m1 = fmaxf(m1, __shfl_xor_sync(0xffffffffu, m1, 1));
        m1 = fmaxf(m1, __shfl_xor_sync(0xffffffffu, m1, 2));

        const float mn0 = fmaxf(mr0, m0);
        const float mn1 = fmaxf(mr1, m1);
        const float a0  = __expf(mr0 - mn0);
        const float a1  = __expf(mr1 - mn1);
        mr0 = mn0; mr1 = mn1;

        float r0 = 0.f, r1 = 0.f;
        #pragma unroll
        for (int nt = 0; nt < 16; ++nt) {
            s[nt][0] = __expf(s[nt][0] - mn0);
            s[nt][1] = __expf(s[nt][1] - mn0);
            s[nt][2] = __expf(s[nt][2] - mn1);
            s[nt][3] = __expf(s[nt][3] - mn1);
            r0 += s[nt][0] + s[nt][1];
            r1 += s[nt][2] + s[nt][3];
        }
        r0 += __shfl_xor_sync(0xffffffffu, r0, 1);
        r0 += __shfl_xor_sync(0xffffffffu, r0, 2);
        r1 += __shfl_xor_sync(0xffffffffu, r1, 1);
        r1 += __shfl_xor_sync(0xffffffffu, r1, 2);
        l0 = l0 * a0 + r0;
        l1 = l1 * a1 + r1;
        #pragma unroll
        for (int nt = 0; nt < 8; ++nt) {
            acc_o[nt][0] *= a0;  acc_o[nt][1] *= a0;
            acc_o[nt][2] *= a1;  acc_o[nt][3] *= a1;
        }

        // ---- O += P(fp16) @ V(fp16) ----
        const uint32_t vrow = (uint32_t)(lane & 15);
        #pragma unroll
        for (int u = 0; u < 8; ++u) {
            uint32_t pf[4];
            pf[0] = pack_h2(s[2*u][0],   s[2*u][1]);
            pf[1] = pack_h2(s[2*u][2],   s[2*u][3]);
            pf[2] = pack_h2(s[2*u+1][0], s[2*u+1][1]);
            pf[3] = pack_h2(s[2*u+1][2], s[2*u+1][3]);
            const uint32_t vb = st + ATT_V + (u * 16 + vrow) * 144;
            #pragma unroll
            for (int nt = 0; nt < 8; ++nt) {
                uint32_t bv[2];
                ldsm_x2t(bv, vb + nt * 16);
                mma_f16(acc_o[nt], pf, bv);
            }
        }

        __syncthreads();
        if (kt + 2 < 16) {
            cp_stage(sb, kt & 1, khg, klg, vg, kt + 2, tid);
            CP_COMMIT();
        }
    }

    // ---- epilogue: normalize, split to bf16 hi/lo, write [B,S,1024] ----
    const int b = bh >> 4;
    const int h = bh & 15;
    const float inv0 = 1.f / l0;
    const float inv1 = 1.f / l1;
    const int row0 = q0 + wid * 16 + (lane >> 2);
    const int row1 = row0 + 8;
    #pragma unroll
    for (int nt = 0; nt < 8; ++nt) {
        const int col = h * DEPTH + nt * 8 + (lane & 3) * 2;
        const size_t i0 = ((size_t)b * SEQ + row0) * DM + col;
        const size_t i1 = ((size_t)b * SEQ + row1) * DM + col;
        split_store(g_ah, g_al, i0, acc_o[nt][0] * inv0, acc_o[nt][1] * inv0);
        split_store(g_ah, g_al, i1, acc_o[nt][2] * inv1, acc_o[nt][3] * inv1);
    }
}

// ---------------------------------------------------------------------------
extern "C" void kernel_launch(void* const* d_in, const int* in_sizes, int n_in,
                              void* d_out, int out_size) {
    const float* x  = (const float*)d_in[0];
    const float* wq = (const float*)d_in[1];
    const float* wk = (const float*)d_in[2];
    const float* wv = (const float*)d_in[3];
    const float* wf = (const float*)d_in[4];
    float* out = (float*)d_out;

    cudaFuncSetAttribute(gemm_qkv_mma, cudaFuncAttributeMaxDynamicSharedMemorySize, GEMM_SMEM_BYTES);
    cudaFuncSetAttribute(gemm_out_mma, cudaFuncAttributeMaxDynamicSharedMemorySize, GEMM_SMEM_BYTES);
    cudaFuncSetAttribute(attn_mma,     cudaFuncAttributeMaxDynamicSharedMemorySize, ATT_SMEM);

    // Split conversions
    split_kernel<<<MTOT * DM / 4 / 256, 256>>>(x,  0, MTOT * DM / 4);
    split_kernel<<<DM * DM / 4 / 256,   256>>>(wq, 1, DM * DM / 4);
    split_kernel<<<DM * DM / 4 / 256,   256>>>(wk, 2, DM * DM / 4);
    split_kernel<<<DM * DM / 4 / 256,   256>>>(wv, 3, DM * DM / 4);
    split_kernel<<<DM * DM / 4 / 256,   256>>>(wf, 4, DM * DM / 4);

    // QKV projection (HMMA, epilogue emits split Q/K + fp16 V)
    dim3 g1(DM / 128, MTOT / 128, 3);
    gemm_qkv_mma<<<g1, 256, GEMM_SMEM_BYTES>>>();

    // Attention (HMMA flash)
    dim3 g2(SEQ / 128, NBH);
    attn_mma<<<g2, 256, ATT_SMEM>>>();

    // Final projection (HMMA)
    dim3 g3(DM / 128, MTOT / 128);
    gemm_out_mma<<<g3, 256, GEMM_SMEM_BYTES>>>(out);
}

// round 5
// speedup vs baseline: 3.3654x; 1.0592x over previous
#include <cuda_runtime.h>
#include <cuda_bf16.h>
#include <cuda_fp16.h>
#include <cstdint>

#define DM      1024
#define NHEAD   16
#define DEPTH   64
#define BATCH   4
#define SEQ     2048
#define MTOT    (BATCH*SEQ)   // 8192
#define NBH     (BATCH*NHEAD) // 64

// ---------------------------------------------------------------------------
// Device-global scratch
// ---------------------------------------------------------------------------
__device__ __nv_bfloat16 g_qh[NBH*SEQ*DEPTH], g_ql[NBH*SEQ*DEPTH]; // Q/8 split
__device__ __nv_bfloat16 g_kh[NBH*SEQ*DEPTH], g_kl[NBH*SEQ*DEPTH]; // K split
__device__ __half        g_vh[NBH*SEQ*DEPTH];                      // V fp16
__device__ __nv_bfloat16 g_ah[MTOT*DM], g_al[MTOT*DM];             // attn out split
__device__ __nv_bfloat16 g_xh[MTOT*DM], g_xl[MTOT*DM];             // x split
__device__ __nv_bfloat16 g_wh[4][DM*DM], g_wl[4][DM*DM];           // weights split

// ---------------------------------------------------------------------------
// PTX helpers (base ISA only: valid on plain sm_103 target)
// ---------------------------------------------------------------------------
__device__ __forceinline__ uint32_t smem_u32(const void* p) {
    uint32_t a;
    asm("{ .reg .u64 t; cvta.to.shared.u64 t, %1; cvt.u32.u64 %0, t; }" : "=r"(a) : "l"(p));
    return a;
}
__device__ __forceinline__ void mma_bf16(float d[4], const uint32_t a[4], const uint32_t b[2]) {
    asm volatile(
        "mma.sync.aligned.m16n8k16.row.col.f32.bf16.bf16.f32 "
        "{%0,%1,%2,%3}, {%4,%5,%6,%7}, {%8,%9}, {%0,%1,%2,%3};\n"
        : "+f"(d[0]), "+f"(d[1]), "+f"(d[2]), "+f"(d[3])
        : "r"(a[0]), "r"(a[1]), "r"(a[2]), "r"(a[3]), "r"(b[0]), "r"(b[1]));
}
__device__ __forceinline__ void mma_f16(float d[4], const uint32_t a[4], const uint32_t b[2]) {
    asm volatile(
        "mma.sync.aligned.m16n8k16.row.col.f32.f16.f16.f32 "
        "{%0,%1,%2,%3}, {%4,%5,%6,%7}, {%8,%9}, {%0,%1,%2,%3};\n"
        : "+f"(d[0]), "+f"(d[1]), "+f"(d[2]), "+f"(d[3])
        : "r"(a[0]), "r"(a[1]), "r"(a[2]), "r"(a[3]), "r"(b[0]), "r"(b[1]));
}
__device__ __forceinline__ void ldsm_x4(uint32_t r[4], uint32_t addr) {
    asm volatile("ldmatrix.sync.aligned.m8n8.x4.shared.b16 {%0,%1,%2,%3}, [%4];"
        : "=r"(r[0]), "=r"(r[1]), "=r"(r[2]), "=r"(r[3]) : "r"(addr));
}
__device__ __forceinline__ void ldsm_x2(uint32_t r[2], uint32_t addr) {
    asm volatile("ldmatrix.sync.aligned.m8n8.x2.shared.b16 {%0,%1}, [%2];"
        : "=r"(r[0]), "=r"(r[1]) : "r"(addr));
}
__device__ __forceinline__ void ldsm_x2t(uint32_t r[2], uint32_t addr) {
    asm volatile("ldmatrix.sync.aligned.m8n8.x2.trans.shared.b16 {%0,%1}, [%2];"
        : "=r"(r[0]), "=r"(r[1]) : "r"(addr));
}
__device__ __forceinline__ void cp16(uint32_t saddr, const void* g) {
    asm volatile("cp.async.cg.shared.global [%0], [%1], 16;" :: "r"(saddr), "l"(g));
}
#define CP_COMMIT() asm volatile("cp.async.commit_group;" ::: "memory")
#define CP_WAIT1()  asm volatile("cp.async.wait_group 1;"  ::: "memory")
#define CP_WAIT0()  asm volatile("cp.async.wait_group 0;"  ::: "memory")

__device__ __forceinline__ uint32_t pack_h2(float x, float y) {
    __half2 h = __floats2half2_rn(x, y);
    return *(uint32_t*)&h;
}
__device__ __forceinline__ void split_store(__nv_bfloat16* hi, __nv_bfloat16* lo,
                                            size_t idx, float v0, float v1) {
    __nv_bfloat16 h0 = __float2bfloat16(v0);
    __nv_bfloat16 h1 = __float2bfloat16(v1);
    __nv_bfloat16 e0 = __float2bfloat16(v0 - __bfloat162float(h0));
    __nv_bfloat16 e1 = __float2bfloat16(v1 - __bfloat162float(h1));
    *(__nv_bfloat162*)(hi + idx) = __halves2bfloat162(h0, h1);
    *(__nv_bfloat162*)(lo + idx) = __halves2bfloat162(e0, e1);
}

// ---------------------------------------------------------------------------
// Split fp32 -> (bf16 hi, bf16 lo).  sel: 0=x, 1..4=wq/wk/wv/wf
// ---------------------------------------------------------------------------
__global__ __launch_bounds__(256) void split_kernel(const float* __restrict__ in, int sel, int n4) {
    int i = blockIdx.x * 256 + threadIdx.x;
    if (i >= n4) return;
    __nv_bfloat16 *hi, *lo;
    if (sel == 0) { hi = g_xh;        lo = g_xl; }
    else          { hi = g_wh[sel-1]; lo = g_wl[sel-1]; }

    float4 v = ((const float4*)in)[i];
    __nv_bfloat16 h0 = __float2bfloat16(v.x);
    __nv_bfloat16 h1 = __float2bfloat16(v.y);
    __nv_bfloat16 h2 = __float2bfloat16(v.z);
    __nv_bfloat16 h3 = __float2bfloat16(v.w);
    __nv_bfloat16 l0 = __float2bfloat16(v.x - __bfloat162float(h0));
    __nv_bfloat16 l1 = __float2bfloat16(v.y - __bfloat162float(h1));
    __nv_bfloat16 l2 = __float2bfloat16(v.z - __bfloat162float(h2));
    __nv_bfloat16 l3 = __float2bfloat16(v.w - __bfloat162float(h3));
    ((__nv_bfloat162*)hi)[i*2 + 0] = __halves2bfloat162(h0, h1);
    ((__nv_bfloat162*)hi)[i*2 + 1] = __halves2bfloat162(h2, h3);
    ((__nv_bfloat162*)lo)[i*2 + 0] = __halves2bfloat162(l0, l1);
    ((__nv_bfloat162*)lo)[i*2 + 1] = __halves2bfloat162(l2, l3);
}

// ---------------------------------------------------------------------------
// GEMM v2: CTA tile 128(M) x 256(N), warp tile 64x64 (2x4 warps), K chunk 32.
// cp.async 3-stage pipeline, single __syncthreads per chunk.
// Stage layout (61440 B): Ah 128x80 @0 | Al @10240 | Bh 256x80 @20480 | Bl @40960
// ---------------------------------------------------------------------------
#define STG_SZ    61440
#define NSTG      3
#define GEMM_SMEM (NSTG*STG_SZ)   // 184320

__device__ __forceinline__ void cp_gemm_stage(uint32_t sb, int buf,
        const __nv_bfloat16* __restrict__ Ah, const __nv_bfloat16* __restrict__ Al,
        const __nv_bfloat16* __restrict__ Wh, const __nv_bfloat16* __restrict__ Wl,
        int m0, int n0, int k0, int tid) {
    const uint32_t s0 = sb + buf * STG_SZ;
    #pragma unroll
    for (int i = 0; i < 4; ++i) {            // A hi+lo: 1024 x 16B chunks
        const int idx = tid + i * 256;
        const int arr = idx >> 9;
        const int r   = (idx >> 2) & 127;
        const int col = idx & 3;
        const __nv_bfloat16* src = (arr ? Al : Ah) + (size_t)(m0 + r) * DM + k0 + col * 8;
        cp16(s0 + arr * 10240 + r * 80 + col * 16, src);
    }
    #pragma unroll
    for (int i = 0; i < 8; ++i) {            // B hi+lo: 2048 x 16B chunks
        const int idx = tid + i * 256;
        const int arr = idx >> 10;
        const int r   = (idx >> 2) & 255;
        const int col = idx & 3;
        const __nv_bfloat16* src = (arr ? Wl : Wh) + (size_t)(n0 + r) * DM + k0 + col * 8;
        cp16(s0 + 20480 + arr * 20480 + r * 80 + col * 16, src);
    }
}

// acc[mt][nt][4]: mt 0..3 (16-row subtiles), nt 0..7 (8-col subtiles)
__device__ __forceinline__ void run_tile_v2(const __nv_bfloat16* __restrict__ Ah,
                                            const __nv_bfloat16* __restrict__ Al,
                                            const __nv_bfloat16* __restrict__ Wh,
                                            const __nv_bfloat16* __restrict__ Wl,
                                            int m0, int n0, uint32_t sb,
                                            float acc[4][8][4]) {
    const int tid  = threadIdx.x;
    const int wid  = tid >> 5;
    const int lane = tid & 31;
    const int wm   = wid >> 2;       // 0..1
    const int wn   = wid & 3;        // 0..3

    const uint32_t a_row = (uint32_t)(wm * 64 + (lane & 15));
    const uint32_t a_sel = (uint32_t)((lane >> 4) * 16);
    const uint32_t b_row = (uint32_t)(wn * 64 + (lane & 7) + ((lane >> 4) & 1) * 8);
    const uint32_t b_sel = (uint32_t)(((lane >> 3) & 1) * 16);

    cp_gemm_stage(sb, 0, Ah, Al, Wh, Wl, m0, n0, 0,  tid); CP_COMMIT();
    cp_gemm_stage(sb, 1, Ah, Al, Wh, Wl, m0, n0, 32, tid); CP_COMMIT();

    #pragma unroll 1
    for (int c = 0; c < 32; ++c) {
        if (c == 31) { CP_WAIT0(); } else { CP_WAIT1(); }
        __syncthreads();
        if (c + 2 < 32) {
            cp_gemm_stage(sb, (c + 2) % NSTG, Ah, Al, Wh, Wl, m0, n0, (c + 2) * 32, tid);
            CP_COMMIT();
        }
        const uint32_t st = sb + (c % NSTG) * STG_SZ;
        #pragma unroll
        for (int ks = 0; ks < 2; ++ks) {
            uint32_t bh[4][4], bl[4][4];
            #pragma unroll
            for (int p = 0; p < 4; ++p) {
                const uint32_t bd = st + 20480 + (b_row + p * 16) * 80 + ks * 32 + b_sel;
                ldsm_x4(bh[p], bd);
                ldsm_x4(bl[p], bd + 20480);
            }
            #pragma unroll
            for (int mt = 0; mt < 4; ++mt) {
                uint32_t ah[4], al[4];
                const uint32_t ad = st + (a_row + mt * 16) * 80 + ks * 32 + a_sel;
                ldsm_x4(ah, ad);
                ldsm_x4(al, ad + 10240);
                #pragma unroll
                for (int p = 0; p < 4; ++p) {
                    mma_bf16(acc[mt][2*p],   ah, bh[p]);
                    mma_bf16(acc[mt][2*p],   ah, bl[p]);
                    mma_bf16(acc[mt][2*p],   al, bh[p]);
                    mma_bf16(acc[mt][2*p+1], ah, bh[p] + 2);
                    mma_bf16(acc[mt][2*p+1], ah, bl[p] + 2);
                    mma_bf16(acc[mt][2*p+1], al, bh[p] + 2);
                }
            }
        }
    }
}

// ---------------------------------------------------------------------------
// QKV projection: grid (4, 64, 3); epilogue writes split-bf16 Q/K, fp16 V
// ---------------------------------------------------------------------------
__global__ __launch_bounds__(256, 1) void gemm_qkv_mma() {
    extern __shared__ char smem[];
    const uint32_t sb = smem_u32(smem);
    const int z  = blockIdx.z;
    const int m0 = blockIdx.y * 128;
    const int n0 = blockIdx.x * 256;

    float acc[4][8][4];
    #pragma unroll
    for (int a = 0; a < 4; ++a)
        #pragma unroll
        for (int b = 0; b < 8; ++b)
            #pragma unroll
            for (int cc = 0; cc < 4; ++cc) acc[a][b][cc] = 0.f;

    run_tile_v2(g_xh, g_xl, g_wh[z], g_wl[z], m0, n0, sb, acc);

    const int wid  = threadIdx.x >> 5;
    const int lane = threadIdx.x & 31;
    const int wm   = wid >> 2;
    const int wn   = wid & 3;

    #pragma unroll
    for (int mt = 0; mt < 4; ++mt) {
        #pragma unroll
        for (int nt = 0; nt < 8; ++nt) {
            const int col = n0 + wn * 64 + nt * 8 + (lane & 3) * 2;
            const int h   = col >> 6;
            const int dd  = col & 63;
            #pragma unroll
            for (int half = 0; half < 2; ++half) {
                const int row = m0 + wm * 64 + mt * 16 + (lane >> 2) + half * 8;
                const int bb  = row >> 11;
                const int ss  = row & 2047;
                const size_t idx = (((size_t)bb * NHEAD + h) * SEQ + ss) * DEPTH + dd;
                float v0 = acc[mt][nt][half * 2];
                float v1 = acc[mt][nt][half * 2 + 1];
                if (z == 0) {
                    split_store(g_qh, g_ql, idx, v0 * 0.125f, v1 * 0.125f);
                } else if (z == 1) {
                    split_store(g_kh, g_kl, idx, v0, v1);
                } else {
                    *(__half2*)(g_vh + idx) = __floats2half2_rn(v0, v1);
                }
            }
        }
    }
}

// ---------------------------------------------------------------------------
// Output projection: grid (4, 64); plain [8192,1024] epilogue
// ---------------------------------------------------------------------------
__global__ __launch_bounds__(256, 1) void gemm_out_mma(float* __restrict__ out) {
    extern __shared__ char smem[];
    const uint32_t sb = smem_u32(smem);
    const int m0 = blockIdx.y * 128;
    const int n0 = blockIdx.x * 256;

    float acc[4][8][4];
    #pragma unroll
    for (int a = 0; a < 4; ++a)
        #pragma unroll
        for (int b = 0; b < 8; ++b)
            #pragma unroll
            for (int cc = 0; cc < 4; ++cc) acc[a][b][cc] = 0.f;

    run_tile_v2(g_ah, g_al, g_wh[3], g_wl[3], m0, n0, sb, acc);

    const int wid  = threadIdx.x >> 5;
    const int lane = threadIdx.x & 31;
    const int wm   = wid >> 2;
    const int wn   = wid & 3;

    #pragma unroll
    for (int mt = 0; mt < 4; ++mt) {
        #pragma unroll
        for (int nt = 0; nt < 8; ++nt) {
            const int col = n0 + wn * 64 + nt * 8 + (lane & 3) * 2;
            #pragma unroll
            for (int half = 0; half < 2; ++half) {
                const int row = m0 + wm * 64 + mt * 16 + (lane >> 2) + half * 8;
                *(float2*)(out + (size_t)row * DM + col) =
                    make_float2(acc[mt][nt][half * 2], acc[mt][nt][half * 2 + 1]);
            }
        }
    }
}

// ---------------------------------------------------------------------------
// HMMA flash attention (unchanged from round 4).
// grid (SEQ/128=16, 64 bh), 256 threads = 8 warps, warp = 16 query rows.
// ---------------------------------------------------------------------------
#define ATT_QH    0
#define ATT_QL    18432
#define ATT_STG   36864
#define ATT_STGSZ 55296
#define ATT_KH    0
#define ATT_KL    18432
#define ATT_V     36864
#define ATT_SMEM  (ATT_STG + 2*ATT_STGSZ)   // 147456

__device__ __forceinline__ void cp_tile16(uint32_t sdst, const void* gsrc, int tid) {
    #pragma unroll
    for (int i = 0; i < 4; ++i) {
        const int c = tid + i * 256;
        const int row = c >> 3;
        const int col = c & 7;
        cp16(sdst + row * 144 + col * 16, (const char*)gsrc + c * 16);
    }
}
__device__ __forceinline__ void cp_stage(uint32_t sb, int buf,
                                         const __nv_bfloat16* kh, const __nv_bfloat16* kl,
                                         const __half* v, int kt, int tid) {
    const uint32_t s0 = sb + ATT_STG + buf * ATT_STGSZ;
    const size_t go = (size_t)kt * 128 * DEPTH;
    cp_tile16(s0 + ATT_KH, kh + go, tid);
    cp_tile16(s0 + ATT_KL, kl + go, tid);
    cp_tile16(s0 + ATT_V,  v  + go, tid);
}

__global__ __launch_bounds__(256, 1) void attn_mma() {
    extern __shared__ char smc[];
    const uint32_t sb = smem_u32(smc);
    const int tid  = threadIdx.x;
    const int wid  = tid >> 5;
    const int lane = tid & 31;
    const int bh   = blockIdx.y;
    const int q0   = blockIdx.x * 128;

    const size_t base = (size_t)bh * SEQ * DEPTH;
    const __nv_bfloat16* qhg = g_qh + base + (size_t)q0 * DEPTH;
    const __nv_bfloat16* qlg = g_ql + base + (size_t)q0 * DEPTH;
    const __nv_bfloat16* khg = g_kh + base;
    const __nv_bfloat16* klg = g_kl + base;
    const __half*        vg  = g_vh + base;

    cp_tile16(sb + ATT_QH, qhg, tid);
    cp_tile16(sb + ATT_QL, qlg, tid);
    cp_stage(sb, 0, khg, klg, vg, 0, tid);
    CP_COMMIT();
    cp_stage(sb, 1, khg, klg, vg, 1, tid);
    CP_COMMIT();
    CP_WAIT1();
    __syncthreads();

    uint32_t qh_f[4][4], ql_f[4][4];
    {
        const uint32_t qrow = (uint32_t)(wid * 16 + (lane & 15));
        const uint32_t qcol = (uint32_t)(((lane >> 4) & 1) * 16);
        #pragma unroll
        for (int ks = 0; ks < 4; ++ks) {
            const uint32_t ad = sb + ATT_QH + qrow * 144 + ks * 32 + qcol;
            ldsm_x4(qh_f[ks], ad);
            ldsm_x4(ql_f[ks], ad + (ATT_QL - ATT_QH));
        }
    }

    float acc_o[8][4];
    #pragma unroll
    for (int nt = 0; nt < 8; ++nt)
        #pragma unroll
        for (int c = 0; c < 4; ++c) acc_o[nt][c] = 0.f;
    float mr0 = -1e30f, mr1 = -1e30f, l0 = 0.f, l1 = 0.f;

    #pragma unroll 1
    for (int kt = 0; kt < 16; ++kt) {
        if (kt > 0) {
            if (kt < 15) { CP_WAIT1(); } else { CP_WAIT0(); }
            __syncthreads();
        }
        const uint32_t st = sb + ATT_STG + (kt & 1) * ATT_STGSZ;

        float s[16][4];
        #pragma unroll
        for (int nt = 0; nt < 16; ++nt)
            #pragma unroll
            for (int c = 0; c < 4; ++c) s[nt][c] = 0.f;

        const uint32_t krow = (uint32_t)(lane & 7);
        const uint32_t kcol = (uint32_t)(((lane >> 3) & 1) * 16);
        #pragma unroll
        for (int ks = 0; ks < 4; ++ks) {
            #pragma unroll
            for (int nt = 0; nt < 16; ++nt) {
                const uint32_t bd = st + ATT_KH + (nt * 8 + krow) * 144 + ks * 32 + kcol;
                uint32_t bhf[2], blf[2];
                ldsm_x2(bhf, bd);
                ldsm_x2(blf, bd + (ATT_KL - ATT_KH));
                mma_bf16(s[nt], qh_f[ks], bhf);
                mma_bf16(s[nt], qh_f[ks], blf);
                mma_bf16(s[nt], ql_f[ks], bhf);
            }
        }

        float m0 = -1e30f, m1 = -1e30f;
        #pragma unroll
        for (int nt = 0; nt < 16; ++nt) {
            m0 = fmaxf(m0, fmaxf(s[nt][0], s[nt][1]));
            m1 = fmaxf(m1, fmaxf(s[nt][2], s[nt][3]));
        }
        m0 = fmaxf(m0, __shfl_xor_sync(0xffffffffu, m0, 1));
        m0 = fmaxf(m0, __shfl_xor_sync(0xffffffffu, m0, 2));
        m1 = fmaxf(m1, __shfl_xor_sync(0xffffffffu, m1, 1));
        m1 = fmaxf(m1, __shfl_xor_sync(0xffffffffu, m1, 2));

        const float mn0 = fmaxf(mr0, m0);
        const float mn1 = fmaxf(mr1, m1);
        const float a0  = __expf(mr0 - mn0);
        const float a1  = __expf(mr1 - mn1);
        mr0 = mn0; mr1 = mn1;

        float r0 = 0.f, r1 = 0.f;
        #pragma unroll
        for (int nt = 0; nt < 16; ++nt) {
            s[nt][0] = __expf(s[nt][0] - mn0);
            s[nt][1] = __expf(s[nt][1] - mn0);
            s[nt][2] = __expf(s[nt][2] - mn1);
            s[nt][3] = __expf(s[nt][3] - mn1);
            r0 += s[nt][0] + s[nt][1];
            r1 += s[nt][2] + s[nt][3];
        }
        r0 += __shfl_xor_sync(0xffffffffu, r0, 1);
        r0 += __shfl_xor_sync(0xffffffffu, r0, 2);
        r1 += __shfl_xor_sync(0xffffffffu, r1, 1);
        r1 += __shfl_xor_sync(0xffffffffu, r1, 2);
        l0 = l0 * a0 + r0;
        l1 = l1 * a1 + r1;
        #pragma unroll
        for (int nt = 0; nt < 8; ++nt) {
            acc_o[nt][0] *= a0;  acc_o[nt][1] *= a0;
            acc_o[nt][2] *= a1;  acc_o[nt][3] *= a1;
        }

        const uint32_t vrow = (uint32_t)(lane & 15);
        #pragma unroll
        for (int u = 0; u < 8; ++u) {
            uint32_t pf[4];
            pf[0] = pack_h2(s[2*u][0],   s[2*u][1]);
            pf[1] = pack_h2(s[2*u][2],   s[2*u][3]);
            pf[2] = pack_h2(s[2*u+1][0], s[2*u+1][1]);
            pf[3] = pack_h2(s[2*u+1][2], s[2*u+1][3]);
            const uint32_t vb = st + ATT_V + (u * 16 + vrow) * 144;
            #pragma unroll
            for (int nt = 0; nt < 8; ++nt) {
                uint32_t bv[2];
                ldsm_x2t(bv, vb + nt * 16);
                mma_f16(acc_o[nt], pf, bv);
            }
        }

        __syncthreads();
        if (kt + 2 < 16) {
            cp_stage(sb, kt & 1, khg, klg, vg, kt + 2, tid);
            CP_COMMIT();
        }
    }

    const int b = bh >> 4;
    const int h = bh & 15;
    const float inv0 = 1.f / l0;
    const float inv1 = 1.f / l1;
    const int row0 = q0 + wid * 16 + (lane >> 2);
    const int row1 = row0 + 8;
    #pragma unroll
    for (int nt = 0; nt < 8; ++nt) {
        const int col = h * DEPTH + nt * 8 + (lane & 3) * 2;
        const size_t i0 = ((size_t)b * SEQ + row0) * DM + col;
        const size_t i1 = ((size_t)b * SEQ + row1) * DM + col;
        split_store(g_ah, g_al, i0, acc_o[nt][0] * inv0, acc_o[nt][1] * inv0);
        split_store(g_ah, g_al, i1, acc_o[nt][2] * inv1, acc_o[nt][3] * inv1);
    }
}

// ---------------------------------------------------------------------------
extern "C" void kernel_launch(void* const* d_in, const int* in_sizes, int n_in,
                              void* d_out, int out_size) {
    const float* x  = (const float*)d_in[0];
    const float* wq = (const float*)d_in[1];
    const float* wk = (const float*)d_in[2];
    const float* wv = (const float*)d_in[3];
    const float* wf = (const float*)d_in[4];
    float* out = (float*)d_out;

    cudaFuncSetAttribute(gemm_qkv_mma, cudaFuncAttributeMaxDynamicSharedMemorySize, GEMM_SMEM);
    cudaFuncSetAttribute(gemm_out_mma, cudaFuncAttributeMaxDynamicSharedMemorySize, GEMM_SMEM);
    cudaFuncSetAttribute(attn_mma,     cudaFuncAttributeMaxDynamicSharedMemorySize, ATT_SMEM);

    // Split conversions
    split_kernel<<<MTOT * DM / 4 / 256, 256>>>(x,  0, MTOT * DM / 4);
    split_kernel<<<DM * DM / 4 / 256,   256>>>(wq, 1, DM * DM / 4);
    split_kernel<<<DM * DM / 4 / 256,   256>>>(wk, 2, DM * DM / 4);
    split_kernel<<<DM * DM / 4 / 256,   256>>>(wv, 3, DM * DM / 4);
    split_kernel<<<DM * DM / 4 / 256,   256>>>(wf, 4, DM * DM / 4);

    // QKV projection (HMMA v2)
    dim3 g1(DM / 256, MTOT / 128, 3);
    gemm_qkv_mma<<<g1, 256, GEMM_SMEM>>>();

    // Attention (HMMA flash)
    dim3 g2(SEQ / 128, NBH);
    attn_mma<<<g2, 256, ATT_SMEM>>>();

    // Final projection (HMMA v2)
    dim3 g3(DM / 256, MTOT / 128);
    gemm_out_mma<<<g3, 256, GEMM_SMEM>>>(out);
}

// round 6
// speedup vs baseline: 4.8927x; 1.4538x over previous
#include <cuda_runtime.h>
#include <cuda_bf16.h>
#include <cuda_fp16.h>
#include <cstdint>

#define DM      1024
#define NHEAD   16
#define DEPTH   64
#define BATCH   4
#define SEQ     2048
#define MTOT    (BATCH*SEQ)   // 8192
#define NBH     (BATCH*NHEAD) // 64

// ---------------------------------------------------------------------------
// Device-global scratch (fp16 everywhere; weights pre-scaled by 32)
// ---------------------------------------------------------------------------
__device__ __half g_q16[NBH*SEQ*DEPTH];    // Q * (1/8): fp16
__device__ __half g_k16[NBH*SEQ*DEPTH];    // K: fp16
__device__ __half g_v16[NBH*SEQ*DEPTH];    // V: fp16
__device__ __half g_a16[MTOT*DM];          // attention out: fp16
__device__ __half g_x16[MTOT*DM];          // x: fp16 (single)
__device__ __half g_w16h[4][DM*DM], g_w16l[4][DM*DM];  // W*32 split hi/lo

// ---------------------------------------------------------------------------
// PTX helpers (base ISA only: valid on plain sm_103 target)
// ---------------------------------------------------------------------------
__device__ __forceinline__ uint32_t smem_u32(const void* p) {
    uint32_t a;
    asm("{ .reg .u64 t; cvta.to.shared.u64 t, %1; cvt.u32.u64 %0, t; }" : "=r"(a) : "l"(p));
    return a;
}
__device__ __forceinline__ void mma_f16(float d[4], const uint32_t a[4], const uint32_t b[2]) {
    asm volatile(
        "mma.sync.aligned.m16n8k16.row.col.f32.f16.f16.f32 "
        "{%0,%1,%2,%3}, {%4,%5,%6,%7}, {%8,%9}, {%0,%1,%2,%3};\n"
        : "+f"(d[0]), "+f"(d[1]), "+f"(d[2]), "+f"(d[3])
        : "r"(a[0]), "r"(a[1]), "r"(a[2]), "r"(a[3]), "r"(b[0]), "r"(b[1]));
}
__device__ __forceinline__ void ldsm_x4(uint32_t r[4], uint32_t addr) {
    asm volatile("ldmatrix.sync.aligned.m8n8.x4.shared.b16 {%0,%1,%2,%3}, [%4];"
        : "=r"(r[0]), "=r"(r[1]), "=r"(r[2]), "=r"(r[3]) : "r"(addr));
}
__device__ __forceinline__ void ldsm_x2(uint32_t r[2], uint32_t addr) {
    asm volatile("ldmatrix.sync.aligned.m8n8.x2.shared.b16 {%0,%1}, [%2];"
        : "=r"(r[0]), "=r"(r[1]) : "r"(addr));
}
__device__ __forceinline__ void ldsm_x2t(uint32_t r[2], uint32_t addr) {
    asm volatile("ldmatrix.sync.aligned.m8n8.x2.trans.shared.b16 {%0,%1}, [%2];"
        : "=r"(r[0]), "=r"(r[1]) : "r"(addr));
}
__device__ __forceinline__ void cp16(uint32_t saddr, const void* g) {
    asm volatile("cp.async.cg.shared.global [%0], [%1], 16;" :: "r"(saddr), "l"(g));
}
#define CP_COMMIT() asm volatile("cp.async.commit_group;" ::: "memory")
#define CP_WAIT1()  asm volatile("cp.async.wait_group 1;"  ::: "memory")
#define CP_WAIT0()  asm volatile("cp.async.wait_group 0;"  ::: "memory")

__device__ __forceinline__ uint32_t pack_h2(float x, float y) {
    __half2 h = __floats2half2_rn(x, y);
    return *(uint32_t*)&h;
}

// ---------------------------------------------------------------------------
// Split kernels.
// sel 0: x -> fp16 single.  sel 1..4: W*32 -> fp16 hi + fp16 lo.
// ---------------------------------------------------------------------------
__global__ __launch_bounds__(256) void split_kernel(const float* __restrict__ in, int sel, int n4) {
    int i = blockIdx.x * 256 + threadIdx.x;
    if (i >= n4) return;
    float4 v = ((const float4*)in)[i];
    if (sel == 0) {
        ((__half2*)g_x16)[i*2 + 0] = __floats2half2_rn(v.x, v.y);
        ((__half2*)g_x16)[i*2 + 1] = __floats2half2_rn(v.z, v.w);
        return;
    }
    __half* hi = g_w16h[sel-1];
    __half* lo = g_w16l[sel-1];
    v.x *= 32.f; v.y *= 32.f; v.z *= 32.f; v.w *= 32.f;
    __half h0 = __float2half_rn(v.x);
    __half h1 = __float2half_rn(v.y);
    __half h2 = __float2half_rn(v.z);
    __half h3 = __float2half_rn(v.w);
    __half l0 = __float2half_rn(v.x - __half2float(h0));
    __half l1 = __float2half_rn(v.y - __half2float(h1));
    __half l2 = __float2half_rn(v.z - __half2float(h2));
    __half l3 = __float2half_rn(v.w - __half2float(h3));
    ((__half2*)hi)[i*2 + 0] = __halves2half2(h0, h1);
    ((__half2*)hi)[i*2 + 1] = __halves2half2(h2, h3);
    ((__half2*)lo)[i*2 + 0] = __halves2half2(l0, l1);
    ((__half2*)lo)[i*2 + 1] = __halves2half2(l2, l3);
}

// ---------------------------------------------------------------------------
// GEMM v3: CTA 128(M) x 256(N), warp tile 64x64 (2x4 warps), K chunk 32.
// A: single fp16. W: fp16 hi+lo (2-pass). cp.async 3-stage.
// Stage (51200 B): A 128x80 @0 | Wh 256x80 @10240 | Wl @30720
// ---------------------------------------------------------------------------
#define STG_SZ    51200
#define NSTG      3
#define GEMM_SMEM (NSTG*STG_SZ)   // 153600

__device__ __forceinline__ void cp_gemm_stage(uint32_t sb, int buf,
        const __half* __restrict__ A,
        const __half* __restrict__ Wh, const __half* __restrict__ Wl,
        int m0, int n0, int k0, int tid) {
    const uint32_t s0 = sb + buf * STG_SZ;
    #pragma unroll
    for (int i = 0; i < 2; ++i) {            // A: 512 x 16B chunks
        const int idx = tid + i * 256;
        const int r   = idx >> 2;
        const int col = idx & 3;
        cp16(s0 + r * 80 + col * 16, A + (size_t)(m0 + r) * DM + k0 + col * 8);
    }
    #pragma unroll
    for (int i = 0; i < 8; ++i) {            // W hi+lo: 2048 x 16B chunks
        const int idx = tid + i * 256;
        const int arr = idx >> 10;
        const int r   = (idx >> 2) & 255;
        const int col = idx & 3;
        const __half* src = (arr ? Wl : Wh) + (size_t)(n0 + r) * DM + k0 + col * 8;
        cp16(s0 + 10240 + arr * 20480 + r * 80 + col * 16, src);
    }
}

__device__ __forceinline__ void run_tile_v3(const __half* __restrict__ A,
                                            const __half* __restrict__ Wh,
                                            const __half* __restrict__ Wl,
                                            int m0, int n0, uint32_t sb,
                                            float acc[4][8][4]) {
    const int tid  = threadIdx.x;
    const int wid  = tid >> 5;
    const int lane = tid & 31;
    const int wm   = wid >> 2;
    const int wn   = wid & 3;

    const uint32_t a_row = (uint32_t)(wm * 64 + (lane & 15));
    const uint32_t a_sel = (uint32_t)((lane >> 4) * 16);
    const uint32_t b_row = (uint32_t)(wn * 64 + (lane & 7) + ((lane >> 4) & 1) * 8);
    const uint32_t b_sel = (uint32_t)(((lane >> 3) & 1) * 16);

    cp_gemm_stage(sb, 0, A, Wh, Wl, m0, n0, 0,  tid); CP_COMMIT();
    cp_gemm_stage(sb, 1, A, Wh, Wl, m0, n0, 32, tid); CP_COMMIT();

    #pragma unroll 1
    for (int c = 0; c < 32; ++c) {
        if (c == 31) { CP_WAIT0(); } else { CP_WAIT1(); }
        __syncthreads();
        if (c + 2 < 32) {
            cp_gemm_stage(sb, (c + 2) % NSTG, A, Wh, Wl, m0, n0, (c + 2) * 32, tid);
            CP_COMMIT();
        }
        const uint32_t st = sb + (c % NSTG) * STG_SZ;
        #pragma unroll
        for (int ks = 0; ks < 2; ++ks) {
            uint32_t bh[4][4], bl[4][4];
            #pragma unroll
            for (int p = 0; p < 4; ++p) {
                const uint32_t bd = st + 10240 + (b_row + p * 16) * 80 + ks * 32 + b_sel;
                ldsm_x4(bh[p], bd);
                ldsm_x4(bl[p], bd + 20480);
            }
            #pragma unroll
            for (int mt = 0; mt < 4; ++mt) {
                uint32_t ah[4];
                ldsm_x4(ah, st + (a_row + mt * 16) * 80 + ks * 32 + a_sel);
                #pragma unroll
                for (int p = 0; p < 4; ++p) {
                    mma_f16(acc[mt][2*p],   ah, bh[p]);
                    mma_f16(acc[mt][2*p],   ah, bl[p]);
                    mma_f16(acc[mt][2*p+1], ah, bh[p] + 2);
                    mma_f16(acc[mt][2*p+1], ah, bl[p] + 2);
                }
            }
        }
    }
}

// ---------------------------------------------------------------------------
// QKV projection: grid (4, 64, 3); epilogue writes fp16 Q(x1/256), K, V (x1/32)
// ---------------------------------------------------------------------------
__global__ __launch_bounds__(256, 1) void gemm_qkv_mma() {
    extern __shared__ char smem[];
    const uint32_t sb = smem_u32(smem);
    const int z  = blockIdx.z;
    const int m0 = blockIdx.y * 128;
    const int n0 = blockIdx.x * 256;

    float acc[4][8][4];
    #pragma unroll
    for (int a = 0; a < 4; ++a)
        #pragma unroll
        for (int b = 0; b < 8; ++b)
            #pragma unroll
            for (int cc = 0; cc < 4; ++cc) acc[a][b][cc] = 0.f;

    run_tile_v3(g_x16, g_w16h[z], g_w16l[z], m0, n0, sb, acc);

    const int wid  = threadIdx.x >> 5;
    const int lane = threadIdx.x & 31;
    const int wm   = wid >> 2;
    const int wn   = wid & 3;
    __half* outb = (z == 0) ? g_q16 : (z == 1) ? g_k16 : g_v16;
    const float scale = (z == 0) ? (1.f / 256.f) : (1.f / 32.f);

    #pragma unroll
    for (int mt = 0; mt < 4; ++mt) {
        #pragma unroll
        for (int nt = 0; nt < 8; ++nt) {
            const int col = n0 + wn * 64 + nt * 8 + (lane & 3) * 2;
            const int h   = col >> 6;
            const int dd  = col & 63;
            #pragma unroll
            for (int half = 0; half < 2; ++half) {
                const int row = m0 + wm * 64 + mt * 16 + (lane >> 2) + half * 8;
                const int bb  = row >> 11;
                const int ss  = row & 2047;
                const size_t idx = (((size_t)bb * NHEAD + h) * SEQ + ss) * DEPTH + dd;
                *(__half2*)(outb + idx) = __floats2half2_rn(acc[mt][nt][half*2]   * scale,
                                                            acc[mt][nt][half*2+1] * scale);
            }
        }
    }
}

// ---------------------------------------------------------------------------
// Output projection: grid (4, 64); fp32 epilogue (x1/32)
// ---------------------------------------------------------------------------
__global__ __launch_bounds__(256, 1) void gemm_out_mma(float* __restrict__ out) {
    extern __shared__ char smem[];
    const uint32_t sb = smem_u32(smem);
    const int m0 = blockIdx.y * 128;
    const int n0 = blockIdx.x * 256;

    float acc[4][8][4];
    #pragma unroll
    for (int a = 0; a < 4; ++a)
        #pragma unroll
        for (int b = 0; b < 8; ++b)
            #pragma unroll
            for (int cc = 0; cc < 4; ++cc) acc[a][b][cc] = 0.f;

    run_tile_v3(g_a16, g_w16h[3], g_w16l[3], m0, n0, sb, acc);

    const int wid  = threadIdx.x >> 5;
    const int lane = threadIdx.x & 31;
    const int wm   = wid >> 2;
    const int wn   = wid & 3;

    #pragma unroll
    for (int mt = 0; mt < 4; ++mt) {
        #pragma unroll
        for (int nt = 0; nt < 8; ++nt) {
            const int col = n0 + wn * 64 + nt * 8 + (lane & 3) * 2;
            #pragma unroll
            for (int half = 0; half < 2; ++half) {
                const int row = m0 + wm * 64 + mt * 16 + (lane >> 2) + half * 8;
                *(float2*)(out + (size_t)row * DM + col) =
                    make_float2(acc[mt][nt][half*2] * (1.f/32.f),
                                acc[mt][nt][half*2+1] * (1.f/32.f));
            }
        }
    }
}

// ---------------------------------------------------------------------------
// HMMA flash attention, fp16 single-pass QK + fp16 PV.
// grid (SEQ/128=16, 64 bh), 256 threads = 8 warps, warp = 16 query rows.
// SMEM: Q 128x144B @0 | stage{0,1}: K 128x144B | V 128x144B
// ---------------------------------------------------------------------------
#define ATT_Q     0
#define ATT_STG   18432
#define ATT_STGSZ 36864
#define ATT_K     0
#define ATT_V     18432
#define ATT_SMEM  (ATT_STG + 2*ATT_STGSZ)   // 92160

__device__ __forceinline__ void cp_tile16(uint32_t sdst, const void* gsrc, int tid) {
    #pragma unroll
    for (int i = 0; i < 4; ++i) {
        const int c = tid + i * 256;
        const int row = c >> 3;
        const int col = c & 7;
        cp16(sdst + row * 144 + col * 16, (const char*)gsrc + c * 16);
    }
}
__device__ __forceinline__ void cp_stage(uint32_t sb, int buf,
                                         const __half* k, const __half* v, int kt, int tid) {
    const uint32_t s0 = sb + ATT_STG + buf * ATT_STGSZ;
    const size_t go = (size_t)kt * 128 * DEPTH;
    cp_tile16(s0 + ATT_K, k + go, tid);
    cp_tile16(s0 + ATT_V, v + go, tid);
}

__global__ __launch_bounds__(256, 1) void attn_mma() {
    extern __shared__ char smc[];
    const uint32_t sb = smem_u32(smc);
    const int tid  = threadIdx.x;
    const int wid  = tid >> 5;
    const int lane = tid & 31;
    const int bh   = blockIdx.y;
    const int q0   = blockIdx.x * 128;

    const size_t base = (size_t)bh * SEQ * DEPTH;
    const __half* qg = g_q16 + base + (size_t)q0 * DEPTH;
    const __half* kg = g_k16 + base;
    const __half* vg = g_v16 + base;

    cp_tile16(sb + ATT_Q, qg, tid);
    cp_stage(sb, 0, kg, vg, 0, tid);
    CP_COMMIT();
    cp_stage(sb, 1, kg, vg, 1, tid);
    CP_COMMIT();
    CP_WAIT1();
    __syncthreads();

    uint32_t q_f[4][4];
    {
        const uint32_t qrow = (uint32_t)(wid * 16 + (lane & 15));
        const uint32_t qcol = (uint32_t)(((lane >> 4) & 1) * 16);
        #pragma unroll
        for (int ks = 0; ks < 4; ++ks)
            ldsm_x4(q_f[ks], sb + ATT_Q + qrow * 144 + ks * 32 + qcol);
    }

    float acc_o[8][4];
    #pragma unroll
    for (int nt = 0; nt < 8; ++nt)
        #pragma unroll
        for (int c = 0; c < 4; ++c) acc_o[nt][c] = 0.f;
    float mr0 = -1e30f, mr1 = -1e30f, l0 = 0.f, l1 = 0.f;

    #pragma unroll 1
    for (int kt = 0; kt < 16; ++kt) {
        if (kt > 0) {
            if (kt < 15) { CP_WAIT1(); } else { CP_WAIT0(); }
            __syncthreads();
        }
        const uint32_t st = sb + ATT_STG + (kt & 1) * ATT_STGSZ;

        // ---- S = (Q/8) @ K^T, fp16 single pass ----
        float s[16][4];
        #pragma unroll
        for (int nt = 0; nt < 16; ++nt)
            #pragma unroll
            for (int c = 0; c < 4; ++c) s[nt][c] = 0.f;

        const uint32_t krow = (uint32_t)(lane & 7);
        const uint32_t kcol = (uint32_t)(((lane >> 3) & 1) * 16);
        #pragma unroll
        for (int ks = 0; ks < 4; ++ks) {
            #pragma unroll
            for (int nt = 0; nt < 16; ++nt) {
                uint32_t bf[2];
                ldsm_x2(bf, st + ATT_K + (nt * 8 + krow) * 144 + ks * 32 + kcol);
                mma_f16(s[nt], q_f[ks], bf);
            }
        }

        // ---- online softmax ----
        float m0 = -1e30f, m1 = -1e30f;
        #pragma unroll
        for (int nt = 0; nt < 16; ++nt) {
            m0 = fmaxf(m0, fmaxf(s[nt][0], s[nt][1]));
            m1 = fmaxf(m1, fmaxf(s[nt][2], s[nt][3]));
        }
        m0 = fmaxf(m0, __shfl_xor_sync(0xffffffffu, m0, 1));
        m0 = fmaxf(m0, __shfl_xor_sync(0xffffffffu, m0, 2));
        m1 = fmaxf(m1, __shfl_xor_sync(0xffffffffu, m1, 1));
        m1 = fmaxf(m1, __shfl_xor_sync(0xffffffffu, m1, 2));

        const float mn0 = fmaxf(mr0, m0);
        const float mn1 = fmaxf(mr1, m1);
        const float a0  = __expf(mr0 - mn0);
        const float a1  = __expf(mr1 - mn1);
        mr0 = mn0; mr1 = mn1;

        float r0 = 0.f, r1 = 0.f;
        #pragma unroll
        for (int nt = 0; nt < 16; ++nt) {
            s[nt][0] = __expf(s[nt][0] - mn0);
            s[nt][1] = __expf(s[nt][1] - mn0);
            s[nt][2] = __expf(s[nt][2] - mn1);
            s[nt][3] = __expf(s[nt][3] - mn1);
            r0 += s[nt][0] + s[nt][1];
            r1 += s[nt][2] + s[nt][3];
        }
        r0 += __shfl_xor_sync(0xffffffffu, r0, 1);
        r0 += __shfl_xor_sync(0xffffffffu, r0, 2);
        r1 += __shfl_xor_sync(0xffffffffu, r1, 1);
        r1 += __shfl_xor_sync(0xffffffffu, r1, 2);
        l0 = l0 * a0 + r0;
        l1 = l1 * a1 + r1;
        #pragma unroll
        for (int nt = 0; nt < 8; ++nt) {
            acc_o[nt][0] *= a0;  acc_o[nt][1] *= a0;
            acc_o[nt][2] *= a1;  acc_o[nt][3] *= a1;
        }

        // ---- O += P(fp16) @ V(fp16) ----
        const uint32_t vrow = (uint32_t)(lane & 15);
        #pragma unroll
        for (int u = 0; u < 8; ++u) {
            uint32_t pf[4];
            pf[0] = pack_h2(s[2*u][0],   s[2*u][1]);
            pf[1] = pack_h2(s[2*u][2],   s[2*u][3]);
            pf[2] = pack_h2(s[2*u+1][0], s[2*u+1][1]);
            pf[3] = pack_h2(s[2*u+1][2], s[2*u+1][3]);
            const uint32_t vb = st + ATT_V + (u * 16 + vrow) * 144;
            #pragma unroll
            for (int nt = 0; nt < 8; ++nt) {
                uint32_t bv[2];
                ldsm_x2t(bv, vb + nt * 16);
                mma_f16(acc_o[nt], pf, bv);
            }
        }

        __syncthreads();
        if (kt + 2 < 16) {
            cp_stage(sb, kt & 1, kg, vg, kt + 2, tid);
            CP_COMMIT();
        }
    }

    // ---- epilogue: normalize, write fp16 att [B,S,1024] ----
    const int b = bh >> 4;
    const int h = bh & 15;
    const float inv0 = 1.f / l0;
    const float inv1 = 1.f / l1;
    const int row0 = q0 + wid * 16 + (lane >> 2);
    const int row1 = row0 + 8;
    #pragma unroll
    for (int nt = 0; nt < 8; ++nt) {
        const int col = h * DEPTH + nt * 8 + (lane & 3) * 2;
        const size_t i0 = ((size_t)b * SEQ + row0) * DM + col;
        const size_t i1 = ((size_t)b * SEQ + row1) * DM + col;
        *(__half2*)(g_a16 + i0) = __floats2half2_rn(acc_o[nt][0] * inv0, acc_o[nt][1] * inv0);
        *(__half2*)(g_a16 + i1) = __floats2half2_rn(acc_o[nt][2] * inv1, acc_o[nt][3] * inv1);
    }
}

// ---------------------------------------------------------------------------
extern "C" void kernel_launch(void* const* d_in, const int* in_sizes, int n_in,
                              void* d_out, int out_size) {
    const float* x  = (const float*)d_in[0];
    const float* wq = (const float*)d_in[1];
    const float* wk = (const float*)d_in[2];
    const float* wv = (const float*)d_in[3];
    const float* wf = (const float*)d_in[4];
    float* out = (float*)d_out;

    cudaFuncSetAttribute(gemm_qkv_mma, cudaFuncAttributeMaxDynamicSharedMemorySize, GEMM_SMEM);
    cudaFuncSetAttribute(gemm_out_mma, cudaFuncAttributeMaxDynamicSharedMemorySize, GEMM_SMEM);
    cudaFuncSetAttribute(attn_mma,     cudaFuncAttributeMaxDynamicSharedMemorySize, ATT_SMEM);

    // Conversions
    split_kernel<<<MTOT * DM / 4 / 256, 256>>>(x,  0, MTOT * DM / 4);
    split_kernel<<<DM * DM / 4 / 256,   256>>>(wq, 1, DM * DM / 4);
    split_kernel<<<DM * DM / 4 / 256,   256>>>(wk, 2, DM * DM / 4);
    split_kernel<<<DM * DM / 4 / 256,   256>>>(wv, 3, DM * DM / 4);
    split_kernel<<<DM * DM / 4 / 256,   256>>>(wf, 4, DM * DM / 4);

    // QKV projection (fp16 2-pass HMMA)
    dim3 g1(DM / 256, MTOT / 128, 3);
    gemm_qkv_mma<<<g1, 256, GEMM_SMEM>>>();

    // Attention (fp16 HMMA flash)
    dim3 g2(SEQ / 128, NBH);
    attn_mma<<<g2, 256, ATT_SMEM>>>();

    // Final projection (fp16 2-pass HMMA)
    dim3 g3(DM / 256, MTOT / 128);
    gemm_out_mma<<<g3, 256, GEMM_SMEM>>>(out);
}

// round 7
// speedup vs baseline: 6.5731x; 1.3434x over previous
#include <cuda_runtime.h>
#include <cuda_bf16.h>
#include <cuda_fp16.h>
#include <cstdint>

#define DM      1024
#define NHEAD   16
#define DEPTH   64
#define BATCH   4
#define SEQ     2048
#define MTOT    (BATCH*SEQ)   // 8192
#define NBH     (BATCH*NHEAD) // 64

// ---------------------------------------------------------------------------
// Device-global scratch (fp16 everywhere)
// ---------------------------------------------------------------------------
__device__ __half g_q16[NBH*SEQ*DEPTH];    // Q * (1/8): fp16
__device__ __half g_k16[NBH*SEQ*DEPTH];    // K: fp16
__device__ __half g_v16[NBH*SEQ*DEPTH];    // V: fp16
__device__ __half g_a16[MTOT*DM];          // attention out: fp16
__device__ __half g_x16[MTOT*DM];          // x: fp16
__device__ __half g_w16[4][DM*DM];         // weights: fp16 single

// ---------------------------------------------------------------------------
// PTX helpers (base ISA only: valid on plain sm_103 target)
// ---------------------------------------------------------------------------
__device__ __forceinline__ uint32_t smem_u32(const void* p) {
    uint32_t a;
    asm("{ .reg .u64 t; cvta.to.shared.u64 t, %1; cvt.u32.u64 %0, t; }" : "=r"(a) : "l"(p));
    return a;
}
__device__ __forceinline__ void mma_f16(float d[4], const uint32_t a[4], const uint32_t b[2]) {
    asm volatile(
        "mma.sync.aligned.m16n8k16.row.col.f32.f16.f16.f32 "
        "{%0,%1,%2,%3}, {%4,%5,%6,%7}, {%8,%9}, {%0,%1,%2,%3};\n"
        : "+f"(d[0]), "+f"(d[1]), "+f"(d[2]), "+f"(d[3])
        : "r"(a[0]), "r"(a[1]), "r"(a[2]), "r"(a[3]), "r"(b[0]), "r"(b[1]));
}
__device__ __forceinline__ void ldsm_x4(uint32_t r[4], uint32_t addr) {
    asm volatile("ldmatrix.sync.aligned.m8n8.x4.shared.b16 {%0,%1,%2,%3}, [%4];"
        : "=r"(r[0]), "=r"(r[1]), "=r"(r[2]), "=r"(r[3]) : "r"(addr));
}
__device__ __forceinline__ void ldsm_x2(uint32_t r[2], uint32_t addr) {
    asm volatile("ldmatrix.sync.aligned.m8n8.x2.shared.b16 {%0,%1}, [%2];"
        : "=r"(r[0]), "=r"(r[1]) : "r"(addr));
}
__device__ __forceinline__ void ldsm_x2t(uint32_t r[2], uint32_t addr) {
    asm volatile("ldmatrix.sync.aligned.m8n8.x2.trans.shared.b16 {%0,%1}, [%2];"
        : "=r"(r[0]), "=r"(r[1]) : "r"(addr));
}
__device__ __forceinline__ void cp16(uint32_t saddr, const void* g) {
    asm volatile("cp.async.cg.shared.global [%0], [%1], 16;" :: "r"(saddr), "l"(g));
}
#define CP_COMMIT() asm volatile("cp.async.commit_group;" ::: "memory")
#define CP_WAIT1()  asm volatile("cp.async.wait_group 1;"  ::: "memory")
#define CP_WAIT0()  asm volatile("cp.async.wait_group 0;"  ::: "memory")

__device__ __forceinline__ uint32_t pack_h2(float x, float y) {
    __half2 h = __floats2half2_rn(x, y);
    return *(uint32_t*)&h;
}

// ---------------------------------------------------------------------------
// Conversion: fp32 -> fp16.  sel 0 = x, 1..4 = wq/wk/wv/wf
// ---------------------------------------------------------------------------
__global__ __launch_bounds__(256) void split_kernel(const float* __restrict__ in, int sel, int n4) {
    int i = blockIdx.x * 256 + threadIdx.x;
    if (i >= n4) return;
    __half* dst = (sel == 0) ? g_x16 : g_w16[sel-1];
    float4 v = ((const float4*)in)[i];
    ((__half2*)dst)[i*2 + 0] = __floats2half2_rn(v.x, v.y);
    ((__half2*)dst)[i*2 + 1] = __floats2half2_rn(v.z, v.w);
}

// ---------------------------------------------------------------------------
// GEMM v4: CTA 128(M) x 256(N), warp tile 64x64 (2x4 warps), K chunk 32.
// Single-pass fp16. cp.async 3-stage.
// Stage (30720 B): A 128x80 @0 | W 256x80 @10240
// ---------------------------------------------------------------------------
#define STG_SZ    30720
#define NSTG      3
#define GEMM_SMEM (NSTG*STG_SZ)   // 92160

__device__ __forceinline__ void cp_gemm_stage(uint32_t sb, int buf,
        const __half* __restrict__ A, const __half* __restrict__ W,
        int m0, int n0, int k0, int tid) {
    const uint32_t s0 = sb + buf * STG_SZ;
    #pragma unroll
    for (int i = 0; i < 2; ++i) {            // A: 512 x 16B chunks
        const int idx = tid + i * 256;
        const int r   = idx >> 2;
        const int col = idx & 3;
        cp16(s0 + r * 80 + col * 16, A + (size_t)(m0 + r) * DM + k0 + col * 8);
    }
    #pragma unroll
    for (int i = 0; i < 4; ++i) {            // W: 1024 x 16B chunks
        const int idx = tid + i * 256;
        const int r   = idx >> 2;
        const int col = idx & 3;
        cp16(s0 + 10240 + r * 80 + col * 16, W + (size_t)(n0 + r) * DM + k0 + col * 8);
    }
}

__device__ __forceinline__ void run_tile_v4(const __half* __restrict__ A,
                                            const __half* __restrict__ W,
                                            int m0, int n0, uint32_t sb,
                                            float acc[4][8][4]) {
    const int tid  = threadIdx.x;
    const int wid  = tid >> 5;
    const int lane = tid & 31;
    const int wm   = wid >> 2;
    const int wn   = wid & 3;

    const uint32_t a_row = (uint32_t)(wm * 64 + (lane & 15));
    const uint32_t a_sel = (uint32_t)((lane >> 4) * 16);
    const uint32_t b_row = (uint32_t)(wn * 64 + (lane & 7) + ((lane >> 4) & 1) * 8);
    const uint32_t b_sel = (uint32_t)(((lane >> 3) & 1) * 16);

    cp_gemm_stage(sb, 0, A, W, m0, n0, 0,  tid); CP_COMMIT();
    cp_gemm_stage(sb, 1, A, W, m0, n0, 32, tid); CP_COMMIT();

    #pragma unroll 1
    for (int c = 0; c < 32; ++c) {
        if (c == 31) { CP_WAIT0(); } else { CP_WAIT1(); }
        __syncthreads();
        if (c + 2 < 32) {
            cp_gemm_stage(sb, (c + 2) % NSTG, A, W, m0, n0, (c + 2) * 32, tid);
            CP_COMMIT();
        }
        const uint32_t st = sb + (c % NSTG) * STG_SZ;
        #pragma unroll
        for (int ks = 0; ks < 2; ++ks) {
            uint32_t bf[4][4];
            #pragma unroll
            for (int p = 0; p < 4; ++p)
                ldsm_x4(bf[p], st + 10240 + (b_row + p * 16) * 80 + ks * 32 + b_sel);
            #pragma unroll
            for (int mt = 0; mt < 4; ++mt) {
                uint32_t ah[4];
                ldsm_x4(ah, st + (a_row + mt * 16) * 80 + ks * 32 + a_sel);
                #pragma unroll
                for (int p = 0; p < 4; ++p) {
                    mma_f16(acc[mt][2*p],   ah, bf[p]);
                    mma_f16(acc[mt][2*p+1], ah, bf[p] + 2);
                }
            }
        }
    }
}

// ---------------------------------------------------------------------------
// QKV projection: grid (4, 64, 3); epilogue writes fp16 Q(x1/8), K, V
// ---------------------------------------------------------------------------
__global__ __launch_bounds__(256, 1) void gemm_qkv_mma() {
    extern __shared__ char smem[];
    const uint32_t sb = smem_u32(smem);
    const int z  = blockIdx.z;
    const int m0 = blockIdx.y * 128;
    const int n0 = blockIdx.x * 256;

    float acc[4][8][4];
    #pragma unroll
    for (int a = 0; a < 4; ++a)
        #pragma unroll
        for (int b = 0; b < 8; ++b)
            #pragma unroll
            for (int cc = 0; cc < 4; ++cc) acc[a][b][cc] = 0.f;

    run_tile_v4(g_x16, g_w16[z], m0, n0, sb, acc);

    const int wid  = threadIdx.x >> 5;
    const int lane = threadIdx.x & 31;
    const int wm   = wid >> 2;
    const int wn   = wid & 3;
    __half* outb = (z == 0) ? g_q16 : (z == 1) ? g_k16 : g_v16;
    const float scale = (z == 0) ? 0.125f : 1.f;

    #pragma unroll
    for (int mt = 0; mt < 4; ++mt) {
        #pragma unroll
        for (int nt = 0; nt < 8; ++nt) {
            const int col = n0 + wn * 64 + nt * 8 + (lane & 3) * 2;
            const int h   = col >> 6;
            const int dd  = col & 63;
            #pragma unroll
            for (int half = 0; half < 2; ++half) {
                const int row = m0 + wm * 64 + mt * 16 + (lane >> 2) + half * 8;
                const int bb  = row >> 11;
                const int ss  = row & 2047;
                const size_t idx = (((size_t)bb * NHEAD + h) * SEQ + ss) * DEPTH + dd;
                *(__half2*)(outb + idx) = __floats2half2_rn(acc[mt][nt][half*2]   * scale,
                                                            acc[mt][nt][half*2+1] * scale);
            }
        }
    }
}

// ---------------------------------------------------------------------------
// Output projection: grid (4, 64); fp32 epilogue
// ---------------------------------------------------------------------------
__global__ __launch_bounds__(256, 1) void gemm_out_mma(float* __restrict__ out) {
    extern __shared__ char smem[];
    const uint32_t sb = smem_u32(smem);
    const int m0 = blockIdx.y * 128;
    const int n0 = blockIdx.x * 256;

    float acc[4][8][4];
    #pragma unroll
    for (int a = 0; a < 4; ++a)
        #pragma unroll
        for (int b = 0; b < 8; ++b)
            #pragma unroll
            for (int cc = 0; cc < 4; ++cc) acc[a][b][cc] = 0.f;

    run_tile_v4(g_a16, g_w16[3], m0, n0, sb, acc);

    const int wid  = threadIdx.x >> 5;
    const int lane = threadIdx.x & 31;
    const int wm   = wid >> 2;
    const int wn   = wid & 3;

    #pragma unroll
    for (int mt = 0; mt < 4; ++mt) {
        #pragma unroll
        for (int nt = 0; nt < 8; ++nt) {
            const int col = n0 + wn * 64 + nt * 8 + (lane & 3) * 2;
            #pragma unroll
            for (int half = 0; half < 2; ++half) {
                const int row = m0 + wm * 64 + mt * 16 + (lane >> 2) + half * 8;
                *(float2*)(out + (size_t)row * DM + col) =
                    make_float2(acc[mt][nt][half*2], acc[mt][nt][half*2+1]);
            }
        }
    }
}

// ---------------------------------------------------------------------------
// HMMA flash attention, fp16 single-pass QK + fp16 PV (unchanged).
// grid (SEQ/128=16, 64 bh), 256 threads = 8 warps, warp = 16 query rows.
// ---------------------------------------------------------------------------
#define ATT_Q     0
#define ATT_STG   18432
#define ATT_STGSZ 36864
#define ATT_K     0
#define ATT_V     18432
#define ATT_SMEM  (ATT_STG + 2*ATT_STGSZ)   // 92160

__device__ __forceinline__ void cp_tile16(uint32_t sdst, const void* gsrc, int tid) {
    #pragma unroll
    for (int i = 0; i < 4; ++i) {
        const int c = tid + i * 256;
        const int row = c >> 3;
        const int col = c & 7;
        cp16(sdst + row * 144 + col * 16, (const char*)gsrc + c * 16);
    }
}
__device__ __forceinline__ void cp_stage(uint32_t sb, int buf,
                                         const __half* k, const __half* v, int kt, int tid) {
    const uint32_t s0 = sb + ATT_STG + buf * ATT_STGSZ;
    const size_t go = (size_t)kt * 128 * DEPTH;
    cp_tile16(s0 + ATT_K, k + go, tid);
    cp_tile16(s0 + ATT_V, v + go, tid);
}

__global__ __launch_bounds__(256, 1) void attn_mma() {
    extern __shared__ char smc[];
    const uint32_t sb = smem_u32(smc);
    const int tid  = threadIdx.x;
    const int wid  = tid >> 5;
    const int lane = tid & 31;
    const int bh   = blockIdx.y;
    const int q0   = blockIdx.x * 128;

    const size_t base = (size_t)bh * SEQ * DEPTH;
    const __half* qg = g_q16 + base + (size_t)q0 * DEPTH;
    const __half* kg = g_k16 + base;
    const __half* vg = g_v16 + base;

    cp_tile16(sb + ATT_Q, qg, tid);
    cp_stage(sb, 0, kg, vg, 0, tid);
    CP_COMMIT();
    cp_stage(sb, 1, kg, vg, 1, tid);
    CP_COMMIT();
    CP_WAIT1();
    __syncthreads();

    uint32_t q_f[4][4];
    {
        const uint32_t qrow = (uint32_t)(wid * 16 + (lane & 15));
        const uint32_t qcol = (uint32_t)(((lane >> 4) & 1) * 16);
        #pragma unroll
        for (int ks = 0; ks < 4; ++ks)
            ldsm_x4(q_f[ks], sb + ATT_Q + qrow * 144 + ks * 32 + qcol);
    }

    float acc_o[8][4];
    #pragma unroll
    for (int nt = 0; nt < 8; ++nt)
        #pragma unroll
        for (int c = 0; c < 4; ++c) acc_o[nt][c] = 0.f;
    float mr0 = -1e30f, mr1 = -1e30f, l0 = 0.f, l1 = 0.f;

    #pragma unroll 1
    for (int kt = 0; kt < 16; ++kt) {
        if (kt > 0) {
            if (kt < 15) { CP_WAIT1(); } else { CP_WAIT0(); }
            __syncthreads();
        }
        const uint32_t st = sb + ATT_STG + (kt & 1) * ATT_STGSZ;

        float s[16][4];
        #pragma unroll
        for (int nt = 0; nt < 16; ++nt)
            #pragma unroll
            for (int c = 0; c < 4; ++c) s[nt][c] = 0.f;

        const uint32_t krow = (uint32_t)(lane & 7);
        const uint32_t kcol = (uint32_t)(((lane >> 3) & 1) * 16);
        #pragma unroll
        for (int ks = 0; ks < 4; ++ks) {
            #pragma unroll
            for (int nt = 0; nt < 16; ++nt) {
                uint32_t bf[2];
                ldsm_x2(bf, st + ATT_K + (nt * 8 + krow) * 144 + ks * 32 + kcol);
                mma_f16(s[nt], q_f[ks], bf);
            }
        }

        float m0 = -1e30f, m1 = -1e30f;
        #pragma unroll
        for (int nt = 0; nt < 16; ++nt) {
            m0 = fmaxf(m0, fmaxf(s[nt][0], s[nt][1]));
            m1 = fmaxf(m1, fmaxf(s[nt][2], s[nt][3]));
        }
        m0 = fmaxf(m0, __shfl_xor_sync(0xffffffffu, m0, 1));
        m0 = fmaxf(m0, __shfl_xor_sync(0xffffffffu, m0, 2));
        m1 = fmaxf(m1, __shfl_xor_sync(0xffffffffu, m1, 1));
        m1 = fmaxf(m1, __shfl_xor_sync(0xffffffffu, m1, 2));

        const float mn0 = fmaxf(mr0, m0);
        const float mn1 = fmaxf(mr1, m1);
        const float a0  = __expf(mr0 - mn0);
        const float a1  = __expf(mr1 - mn1);
        mr0 = mn0; mr1 = mn1;

        float r0 = 0.f, r1 = 0.f;
        #pragma unroll
        for (int nt = 0; nt < 16; ++nt) {
            s[nt][0] = __expf(s[nt][0] - mn0);
            s[nt][1] = __expf(s[nt][1] - mn0);
            s[nt][2] = __expf(s[nt][2] - mn1);
            s[nt][3] = __expf(s[nt][3] - mn1);
            r0 += s[nt][0] + s[nt][1];
            r1 += s[nt][2] + s[nt][3];
        }
        r0 += __shfl_xor_sync(0xffffffffu, r0, 1);
        r0 += __shfl_xor_sync(0xffffffffu, r0, 2);
        r1 += __shfl_xor_sync(0xffffffffu, r1, 1);
        r1 += __shfl_xor_sync(0xffffffffu, r1, 2);
        l0 = l0 * a0 + r0;
        l1 = l1 * a1 + r1;
        #pragma unroll
        for (int nt = 0; nt < 8; ++nt) {
            acc_o[nt][0] *= a0;  acc_o[nt][1] *= a0;
            acc_o[nt][2] *= a1;  acc_o[nt][3] *= a1;
        }

        const uint32_t vrow = (uint32_t)(lane & 15);
        #pragma unroll
        for (int u = 0; u < 8; ++u) {
            uint32_t pf[4];
            pf[0] = pack_h2(s[2*u][0],   s[2*u][1]);
            pf[1] = pack_h2(s[2*u][2],   s[2*u][3]);
            pf[2] = pack_h2(s[2*u+1][0], s[2*u+1][1]);
            pf[3] = pack_h2(s[2*u+1][2], s[2*u+1][3]);
            const uint32_t vb = st + ATT_V + (u * 16 + vrow) * 144;
            #pragma unroll
            for (int nt = 0; nt < 8; ++nt) {
                uint32_t bv[2];
                ldsm_x2t(bv, vb + nt * 16);
                mma_f16(acc_o[nt], pf, bv);
            }
        }

        __syncthreads();
        if (kt + 2 < 16) {
            cp_stage(sb, kt & 1, kg, vg, kt + 2, tid);
            CP_COMMIT();
        }
    }

    const int b = bh >> 4;
    const int h = bh & 15;
    const float inv0 = 1.f / l0;
    const float inv1 = 1.f / l1;
    const int row0 = q0 + wid * 16 + (lane >> 2);
    const int row1 = row0 + 8;
    #pragma unroll
    for (int nt = 0; nt < 8; ++nt) {
        const int col = h * DEPTH + nt * 8 + (lane & 3) * 2;
        const size_t i0 = ((size_t)b * SEQ + row0) * DM + col;
        const size_t i1 = ((size_t)b * SEQ + row1) * DM + col;
        *(__half2*)(g_a16 + i0) = __floats2half2_rn(acc_o[nt][0] * inv0, acc_o[nt][1] * inv0);
        *(__half2*)(g_a16 + i1) = __floats2half2_rn(acc_o[nt][2] * inv1, acc_o[nt][3] * inv1);
    }
}

// ---------------------------------------------------------------------------
extern "C" void kernel_launch(void* const* d_in, const int* in_sizes, int n_in,
                              void* d_out, int out_size) {
    const float* x  = (const float*)d_in[0];
    const float* wq = (const float*)d_in[1];
    const float* wk = (const float*)d_in[2];
    const float* wv = (const float*)d_in[3];
    const float* wf = (const float*)d_in[4];
    float* out = (float*)d_out;

    cudaFuncSetAttribute(gemm_qkv_mma, cudaFuncAttributeMaxDynamicSharedMemorySize, GEMM_SMEM);
    cudaFuncSetAttribute(gemm_out_mma, cudaFuncAttributeMaxDynamicSharedMemorySize, GEMM_SMEM);
    cudaFuncSetAttribute(attn_mma,     cudaFuncAttributeMaxDynamicSharedMemorySize, ATT_SMEM);

    // Conversions
    split_kernel<<<MTOT * DM / 4 / 256, 256>>>(x,  0, MTOT * DM / 4);
    split_kernel<<<DM * DM / 4 / 256,   256>>>(wq, 1, DM * DM / 4);
    split_kernel<<<DM * DM / 4 / 256,   256>>>(wk, 2, DM * DM / 4);
    split_kernel<<<DM * DM / 4 / 256,   256>>>(wv, 3, DM * DM / 4);
    split_kernel<<<DM * DM / 4 / 256,   256>>>(wf, 4, DM * DM / 4);

    // QKV projection (fp16 single-pass HMMA)
    dim3 g1(DM / 256, MTOT / 128, 3);
    gemm_qkv_mma<<<g1, 256, GEMM_SMEM>>>();

    // Attention (fp16 HMMA flash)
    dim3 g2(SEQ / 128, NBH);
    attn_mma<<<g2, 256, ATT_SMEM>>>();

    // Final projection (fp16 single-pass HMMA)
    dim3 g3(DM / 256, MTOT / 128);
    gemm_out_mma<<<g3, 256, GEMM_SMEM>>>(out);
}